// round 9
// baseline (speedup 1.0000x reference)
#include <cuda_runtime.h>
#include <cuda_bf16.h>
#include <math.h>
#include <stdint.h>

#define MTOT   8192
#define DMODEL 768
#define NHEADS 12
#define DHEAD  64
#define DMLP   3072
#define SEQ    1024
#define BATCH  8
#define QKVW   (3*DMODEL)

typedef __nv_bfloat16 bf16;

// ---------------- scratch ----------------
__device__ __align__(256) float g_xn [MTOT*DMODEL];
__device__ __align__(256) float g_xn2[MTOT*DMODEL];
__device__ __align__(256) float g_z  [MTOT*DMODEL];
__device__ __align__(256) float g_hid[(size_t)MTOT*DMLP];
__device__ __align__(256) bf16 g_qkv_hi[(size_t)MTOT*QKVW];
__device__ __align__(256) bf16 g_qkv_lo[(size_t)MTOT*QKVW];
__device__ __align__(256) float g_wqkv[QKVW*DMODEL];
__device__ __align__(256) float g_wo  [DMODEL*DMODEL];
__device__ __align__(256) float g_win [DMODEL*DMLP];
__device__ __align__(256) float g_wout[DMLP*DMODEL];
__device__ float g_bqkv[QKVW];
__device__ float g_mid [MTOT*DMODEL];

// ---------------- helpers ----------------
__device__ __forceinline__ uint32_t smem_u32(const void* p) {
    uint32_t a;
    asm("{ .reg .u64 t; cvta.to.shared.u64 t, %1; cvt.u32.u64 %0, t; }" : "=r"(a) : "l"(p));
    return a;
}
#define SW128(o) ((o) ^ (((o) >> 3) & 0x70))

__device__ __forceinline__ void cp16(uint32_t dst, const void* src) {
    asm volatile("cp.async.cg.shared.global [%0], [%1], 16;" :: "r"(dst), "l"(src));
}
#define CP_COMMIT() asm volatile("cp.async.commit_group;" ::: "memory")
#define CP_WAIT(n)  asm volatile("cp.async.wait_group %0;" :: "n"(n) : "memory")

#define LDSM4(r0, r1, r2, r3, addr) \
    asm volatile("ldmatrix.sync.aligned.m8n8.x4.shared.b16 {%0,%1,%2,%3},[%4];" \
        : "=r"(r0), "=r"(r1), "=r"(r2), "=r"(r3) : "r"(addr))
#define LDSM4T(r0, r1, r2, r3, addr) \
    asm volatile("ldmatrix.sync.aligned.m8n8.x4.trans.shared.b16 {%0,%1,%2,%3},[%4];" \
        : "=r"(r0), "=r"(r1), "=r"(r2), "=r"(r3) : "r"(addr))

#define MMA16816(d, a, b0, b1) \
    asm volatile("mma.sync.aligned.m16n8k16.row.col.f32.bf16.bf16.f32 " \
        "{%0,%1,%2,%3},{%4,%5,%6,%7},{%8,%9},{%0,%1,%2,%3};" \
        : "+f"((d)[0]), "+f"((d)[1]), "+f"((d)[2]), "+f"((d)[3]) \
        : "r"((a)[0]), "r"((a)[1]), "r"((a)[2]), "r"((a)[3]), "r"(b0), "r"(b1))

#define MMATF32(d, a, b0, b1) \
    asm volatile("mma.sync.aligned.m16n8k8.row.col.f32.tf32.tf32.f32 " \
        "{%0,%1,%2,%3},{%4,%5,%6,%7},{%8,%9},{%0,%1,%2,%3};" \
        : "+f"((d)[0]), "+f"((d)[1]), "+f"((d)[2]), "+f"((d)[3]) \
        : "r"((a)[0]), "r"((a)[1]), "r"((a)[2]), "r"((a)[3]), "r"(b0), "r"(b1))

__device__ __forceinline__ float to_tf32(float x) {
    uint32_t u;
    asm("cvt.rna.tf32.f32 %0, %1;" : "=r"(u) : "f"(x));
    return __uint_as_float(u);
}
__device__ __forceinline__ float gelu_new_f(float x) {
    float x3 = x * x * x;
    return 0.5f * x * (1.0f + tanhf(0.7978845608028654f * (x + 0.044715f * x3)));
}
__device__ __forceinline__ uint32_t pack_bf162(bf16 a, bf16 b) {
    __nv_bfloat162 t(a, b);
    return *(uint32_t*)&t;
}
__device__ __forceinline__ uint32_t pack_hi2(float a, float b) {
    return pack_bf162(__float2bfloat16(a), __float2bfloat16(b));
}
__device__ __forceinline__ uint32_t pack_lo2(float a, float b) {
    bf16 ha = __float2bfloat16(a), hb = __float2bfloat16(b);
    return pack_bf162(__float2bfloat16(a - __bfloat162float(ha)),
                      __float2bfloat16(b - __bfloat162float(hb)));
}

// ---------------- packs ----------------
__global__ void pack_bqkv_kernel(const float* __restrict__ bQ, const float* __restrict__ bK,
                                 const float* __restrict__ bV) {
    int i = threadIdx.x + blockIdx.x * 256;
    if (i >= QKVW) return;
    g_bqkv[i] = (i < DMODEL) ? bQ[i] * 0.125f : (i < 2 * DMODEL ? bK[i - DMODEL] : bV[i - 2 * DMODEL]);
}

// W_{Q,K,V}[h][d][e] -> g_wqkv[(sel*768 + h*64 + e)][d], Q scaled 1/8
__global__ __launch_bounds__(256)
void pack_qkvw(const float* __restrict__ WQ, const float* __restrict__ WK,
               const float* __restrict__ WV) {
    __shared__ float t[32][33];
    int z = blockIdx.z;
    int sel = z / NHEADS, h = z % NHEADS;
    const float* src = (sel == 0 ? WQ : sel == 1 ? WK : WV) + (size_t)h * DMODEL * DHEAD;
    float scale = sel == 0 ? 0.125f : 1.0f;
    int r0 = blockIdx.y * 32, c0 = blockIdx.x * 32;
    int tr = threadIdx.x >> 5, tc = threadIdx.x & 31;
#pragma unroll
    for (int i = 0; i < 4; i++)
        t[tr + i * 8][tc] = src[(size_t)(r0 + tr + i * 8) * DHEAD + c0 + tc];
    __syncthreads();
    int colbase = sel * DMODEL + h * DHEAD + c0;
#pragma unroll
    for (int i = 0; i < 4; i++) {
        int cc = tr + i * 8;
        g_wqkv[(size_t)(colbase + cc) * DMODEL + r0 + tc] = to_tf32(t[tc][cc] * scale);
    }
}

// WO/Win/Wout transposes in one launch (flat 32x32 tile index)
__global__ __launch_bounds__(256)
void pack_mlpw(const float* __restrict__ WO, const float* __restrict__ Win,
               const float* __restrict__ Wout) {
    __shared__ float t[32][33];
    int ti = blockIdx.x;
    const float* src; float* dst; int R, C, rt, ct;
    if (ti < 576)        { src = WO;   dst = g_wo;   R = DMODEL; C = DMODEL; rt = ti / 24;  ct = ti % 24; }
    else if (ti < 2880)  { int u = ti - 576;  src = Win;  dst = g_win;  R = DMODEL; C = DMLP;   rt = u / 96; ct = u % 96; }
    else                 { int u = ti - 2880; src = Wout; dst = g_wout; R = DMLP;   C = DMODEL; rt = u / 24; ct = u % 24; }
    int r0 = rt * 32, c0 = ct * 32;
    int tr = threadIdx.x >> 5, tc = threadIdx.x & 31;
#pragma unroll
    for (int i = 0; i < 4; i++)
        t[tr + i * 8][tc] = src[(size_t)(r0 + tr + i * 8) * C + c0 + tc];
    __syncthreads();
#pragma unroll
    for (int i = 0; i < 4; i++) {
        int cc = tr + i * 8;
        dst[(size_t)(c0 + cc) * R + r0 + tc] = to_tf32(t[tc][cc]);
    }
}

// ---------------- layernorm -> tf32-rounded f32 ----------------
__global__ __launch_bounds__(256)
void ln_kernel(const float* __restrict__ x, const float* __restrict__ w, const float* __restrict__ b,
               float* __restrict__ y) {
    __shared__ float ws[8], wq[8], stats[2];
    int row = blockIdx.x, tid = threadIdx.x;
    const float* xr = x + (size_t)row * DMODEL;
    float v0 = xr[tid], v1 = xr[tid + 256], v2 = xr[tid + 512];
    float s = v0 + v1 + v2, sq = v0 * v0 + v1 * v1 + v2 * v2;
#pragma unroll
    for (int o = 16; o > 0; o >>= 1) {
        s  += __shfl_xor_sync(0xffffffffu, s,  o);
        sq += __shfl_xor_sync(0xffffffffu, sq, o);
    }
    if ((tid & 31) == 0) { ws[tid >> 5] = s; wq[tid >> 5] = sq; }
    __syncthreads();
    if (tid == 0) {
        float ts = 0.f, tq = 0.f;
#pragma unroll
        for (int i = 0; i < 8; i++) { ts += ws[i]; tq += wq[i]; }
        float mean = ts * (1.0f / DMODEL);
        float var  = tq * (1.0f / DMODEL) - mean * mean;
        stats[0] = mean; stats[1] = rsqrtf(var + 1e-5f);
    }
    __syncthreads();
    float mean = stats[0], rstd = stats[1];
    size_t base = (size_t)row * DMODEL;
#pragma unroll
    for (int u = 0; u < 3; u++) {
        int c = tid + u * 256;
        float yv = ((u == 0 ? v0 : u == 1 ? v1 : v2) - mean) * rstd * w[c] + b[c];
        y[base + c] = to_tf32(yv);
    }
}

// ---------------- TF32 GEMM: C[M,N] = A[M,K] * B[N,K]^T ----------------
// 256x128 CTA tile, KC=32, 3-stage cp.async, 512 threads (16 warps 4x4), 64x32 warp tile.
// EPI: 1 = bias+gelu->tf32 f32 ; 2 = bias+resid->f32 ; 3 = bias->bf16 hi/lo
#define TTILE_A 32768
#define TTILE_B 16384
#define TSTG    (TTILE_A + TTILE_B)
#define TSMEM   (1024 + 3*TSTG)

__device__ __forceinline__ void stage_tf(uint32_t tb, const float* A, const float* B,
                                         int k0, int K, int tid) {
#pragma unroll
    for (int it = 0; it < 4; it++) {
        int idx = tid + it * 512;
        int row = idx >> 3, seg = idx & 7;
        cp16(tb + SW128((uint32_t)(row * 128 + seg * 16)), A + (size_t)row * K + k0 + seg * 4);
    }
#pragma unroll
    for (int it = 0; it < 2; it++) {
        int idx = tid + it * 512;
        int row = idx >> 3, seg = idx & 7;
        cp16(tb + TTILE_A + SW128((uint32_t)(row * 128 + seg * 16)), B + (size_t)row * K + k0 + seg * 4);
    }
    CP_COMMIT();
}

template <int EPI>
__global__ __launch_bounds__(512, 1)
void gemm_tf32(const float* __restrict__ A, const float* __restrict__ B,
               const float* __restrict__ bias, const float* __restrict__ R,
               float* __restrict__ C, bf16* __restrict__ Chi, bf16* __restrict__ Clo,
               int N, int K, int NC) {
    extern __shared__ char smraw[];
    uint32_t sb = (smem_u32(smraw) + 1023) & ~1023u;
    int tid = threadIdx.x;
    int row0 = blockIdx.y * 256, col0 = blockIdx.x * 128;
    int wid = tid >> 5, lane = tid & 31;
    int wm = (wid & 3) * 64, wn = (wid >> 2) * 32;

    const float* Ab = A + (size_t)row0 * K;
    const float* Bb = B + (size_t)col0 * K;

    stage_tf(sb,        Ab, Bb, 0,  K, tid);
    stage_tf(sb + TSTG, Ab, Bb, 32, K, tid);

    float acc[4][4][4];
#pragma unroll
    for (int mi = 0; mi < 4; mi++)
#pragma unroll
        for (int ni = 0; ni < 4; ni++)
#pragma unroll
            for (int q = 0; q < 4; q++) acc[mi][ni][q] = 0.f;

    int ar = lane & 15, acol = (lane >> 4) * 16;
    int brt = (lane & 7) + ((lane >> 4) & 1) * 8;
    int bct = ((lane >> 3) & 1) * 16;

    for (int i = 0; i < NC; i++) {
        if (i + 2 < NC) {
            stage_tf(sb + (uint32_t)((i + 2) % 3) * TSTG, Ab, Bb, (i + 2) * 32, K, tid);
            CP_WAIT(2);
        } else {
            CP_WAIT(0);
        }
        __syncthreads();
        uint32_t tb = sb + (uint32_t)(i % 3) * TSTG;
#pragma unroll
        for (int ks = 0; ks < 4; ks++) {
            uint32_t af[4][4], bfr[2][4];
#pragma unroll
            for (int mi = 0; mi < 4; mi++) {
                uint32_t off = SW128((uint32_t)((wm + mi * 16 + ar) * 128 + ks * 32 + acol));
                LDSM4(af[mi][0], af[mi][1], af[mi][2], af[mi][3], tb + off);
            }
#pragma unroll
            for (int nb = 0; nb < 2; nb++) {
                uint32_t off = SW128((uint32_t)((wn + nb * 16 + brt) * 128 + ks * 32 + bct));
                LDSM4(bfr[nb][0], bfr[nb][1], bfr[nb][2], bfr[nb][3], tb + TTILE_A + off);
            }
#pragma unroll
            for (int mi = 0; mi < 4; mi++)
#pragma unroll
                for (int ni = 0; ni < 4; ni++) {
                    int nb = ni >> 1, p = (ni & 1) * 2;
                    MMATF32(acc[mi][ni], af[mi], bfr[nb][p], bfr[nb][p + 1]);
                }
        }
        __syncthreads();
    }

#pragma unroll
    for (int mi = 0; mi < 4; mi++) {
#pragma unroll
        for (int ni = 0; ni < 4; ni++) {
            int r = row0 + wm + mi * 16 + (lane >> 2);
            int c = col0 + wn + ni * 8 + (lane & 3) * 2;
            float b0 = bias[c], b1 = bias[c + 1];
#pragma unroll
            for (int half = 0; half < 2; half++) {
                int rr = r + half * 8;
                float v0 = acc[mi][ni][2 * half]     + b0;
                float v1 = acc[mi][ni][2 * half + 1] + b1;
                if (EPI == 1) {
                    *(float2*)&C[(size_t)rr * N + c] =
                        make_float2(to_tf32(gelu_new_f(v0)), to_tf32(gelu_new_f(v1)));
                } else if (EPI == 3) {
                    *(uint32_t*)&Chi[(size_t)rr * N + c] = pack_hi2(v0, v1);
                    *(uint32_t*)&Clo[(size_t)rr * N + c] = pack_lo2(v0, v1);
                } else {
                    float2 rv = *(const float2*)&R[(size_t)rr * N + c];
                    *(float2*)&C[(size_t)rr * N + c] = make_float2(v0 + rv.x, v1 + rv.y);
                }
            }
        }
    }
}

// ---------------- mma flash attention, split-bf16 ----------------
#define ASTG0 32768
#define ASTG  32768
#define ASMEM (1024 + ASTG0 + 2*ASTG)
#define NEGINF (-1e30f)

__device__ __forceinline__ void attn_stage_kv(uint32_t kb, const bf16* kh, const bf16* kl,
                                              const bf16* vh, const bf16* vl, int tid) {
#pragma unroll
    for (int it = 0; it < 2; it++) {
        int idx = tid + it * 256;
        int row = idx >> 3, seg = idx & 7;
        uint32_t off = SW128((uint32_t)(row * 128 + seg * 16));
        size_t g = (size_t)row * QKVW + seg * 8;
        cp16(kb + off,         kh + g);
        cp16(kb + 8192 + off,  kl + g);
        cp16(kb + 16384 + off, vh + g);
        cp16(kb + 24576 + off, vl + g);
    }
}

__global__ __launch_bounds__(256, 2)
void attn_mma(const bf16* __restrict__ qkvh, const bf16* __restrict__ qkvl,
              float* __restrict__ z) {
    extern __shared__ char smraw[];
    uint32_t sq = (smem_u32(smraw) + 1023) & ~1023u;
    uint32_t sstage = sq + ASTG0;
    int tid = threadIdx.x, wid = tid >> 5, lane = tid & 31;
    int qt = blockIdx.x, h = blockIdx.y, b = blockIdx.z;
    int q0 = qt * 128;
    size_t tokbase = (size_t)b * SEQ * QKVW;
    const bf16* qhp = qkvh + tokbase + (size_t)q0 * QKVW + h * DHEAD;
    const bf16* qlp = qkvl + tokbase + (size_t)q0 * QKVW + h * DHEAD;
    const bf16* khp = qkvh + tokbase + DMODEL + h * DHEAD;
    const bf16* klp = qkvl + tokbase + DMODEL + h * DHEAD;
    const bf16* vhp = qkvh + tokbase + 2 * DMODEL + h * DHEAD;
    const bf16* vlp = qkvl + tokbase + 2 * DMODEL + h * DHEAD;

#pragma unroll
    for (int it = 0; it < 4; it++) {
        int idx = tid + it * 256;
        int row = idx >> 3, seg = idx & 7;
        uint32_t off = SW128((uint32_t)(row * 128 + seg * 16));
        size_t g = (size_t)row * QKVW + seg * 8;
        cp16(sq + off,         qhp + g);
        cp16(sq + 16384 + off, qlp + g);
    }
    CP_COMMIT();
    attn_stage_kv(sstage, khp, klp, vhp, vlp, tid);
    CP_COMMIT();

    float o[8][4];
#pragma unroll
    for (int d = 0; d < 8; d++)
#pragma unroll
        for (int q = 0; q < 4; q++) o[d][q] = 0.f;
    float m0 = NEGINF, m1 = NEGINF, l0 = 0.f, l1 = 0.f;

    int ar = lane & 15, ahalf = lane >> 4;
    int brow = (lane & 7) + ((lane >> 4) << 3);
    int bhalf = (lane >> 3) & 1;
    int vkrow = (lane & 7) + (((lane >> 3) & 1) << 3);
    int vncol = (lane >> 4) * 8;
    int r0g = q0 + wid * 16 + (lane >> 2);

    int nkt = 2 * qt + 2;
    for (int kt = 0; kt < nkt; kt++) {
        __syncthreads();
        if (kt + 1 < nkt) {
            attn_stage_kv(sstage + (uint32_t)((kt + 1) & 1) * ASTG,
                          khp + (size_t)(kt + 1) * 64 * QKVW, klp + (size_t)(kt + 1) * 64 * QKVW,
                          vhp + (size_t)(kt + 1) * 64 * QKVW, vlp + (size_t)(kt + 1) * 64 * QKVW, tid);
            CP_COMMIT();
            CP_WAIT(1);
        } else {
            CP_WAIT(0);
        }
        __syncthreads();
        uint32_t kb = sstage + (uint32_t)(kt & 1) * ASTG;

        float s[8][4];
#pragma unroll
        for (int ni = 0; ni < 8; ni++)
#pragma unroll
            for (int q = 0; q < 4; q++) s[ni][q] = 0.f;
#pragma unroll
        for (int ks = 0; ks < 4; ks++) {
            uint32_t ah[4], al[4];
            uint32_t offa = SW128((uint32_t)((wid * 16 + ar) * 128 + ks * 32 + ahalf * 16));
            LDSM4(ah[0], ah[1], ah[2], ah[3], sq + offa);
            LDSM4(al[0], al[1], al[2], al[3], sq + 16384 + offa);
#pragma unroll
            for (int nb = 0; nb < 4; nb++) {
                uint32_t bh[4], bl[4];
                uint32_t offb = SW128((uint32_t)((nb * 16 + brow) * 128 + ks * 32 + bhalf * 16));
                LDSM4(bh[0], bh[1], bh[2], bh[3], kb + offb);
                LDSM4(bl[0], bl[1], bl[2], bl[3], kb + 8192 + offb);
#pragma unroll
                for (int niL = 0; niL < 2; niL++) {
                    int ni = nb * 2 + niL, p = niL * 2;
                    MMA16816(s[ni], ah, bh[p], bh[p + 1]);
                    MMA16816(s[ni], ah, bl[p], bl[p + 1]);
                    MMA16816(s[ni], al, bh[p], bh[p + 1]);
                }
            }
        }

        if (kt >= 2 * qt) {
            int cbase = kt * 64 + (lane & 3) * 2;
#pragma unroll
            for (int ni = 0; ni < 8; ni++) {
                int c0 = cbase + ni * 8, c1 = c0 + 1;
                if (c0 > r0g)     s[ni][0] = NEGINF;
                if (c1 > r0g)     s[ni][1] = NEGINF;
                if (c0 > r0g + 8) s[ni][2] = NEGINF;
                if (c1 > r0g + 8) s[ni][3] = NEGINF;
            }
        }

        float tm0 = NEGINF, tm1 = NEGINF;
#pragma unroll
        for (int ni = 0; ni < 8; ni++) {
            tm0 = fmaxf(tm0, fmaxf(s[ni][0], s[ni][1]));
            tm1 = fmaxf(tm1, fmaxf(s[ni][2], s[ni][3]));
        }
        tm0 = fmaxf(tm0, __shfl_xor_sync(0xffffffffu, tm0, 1));
        tm0 = fmaxf(tm0, __shfl_xor_sync(0xffffffffu, tm0, 2));
        tm1 = fmaxf(tm1, __shfl_xor_sync(0xffffffffu, tm1, 1));
        tm1 = fmaxf(tm1, __shfl_xor_sync(0xffffffffu, tm1, 2));
        float nm0 = fmaxf(m0, tm0), nm1 = fmaxf(m1, tm1);
        float alpha0 = __expf(m0 - nm0), alpha1 = __expf(m1 - nm1);
        m0 = nm0; m1 = nm1;
        float rs0 = 0.f, rs1 = 0.f;
#pragma unroll
        for (int ni = 0; ni < 8; ni++) {
            s[ni][0] = __expf(s[ni][0] - nm0);
            s[ni][1] = __expf(s[ni][1] - nm0);
            s[ni][2] = __expf(s[ni][2] - nm1);
            s[ni][3] = __expf(s[ni][3] - nm1);
            rs0 += s[ni][0] + s[ni][1];
            rs1 += s[ni][2] + s[ni][3];
        }
        rs0 += __shfl_xor_sync(0xffffffffu, rs0, 1);
        rs0 += __shfl_xor_sync(0xffffffffu, rs0, 2);
        rs1 += __shfl_xor_sync(0xffffffffu, rs1, 1);
        rs1 += __shfl_xor_sync(0xffffffffu, rs1, 2);
        l0 = l0 * alpha0 + rs0;
        l1 = l1 * alpha1 + rs1;
#pragma unroll
        for (int d = 0; d < 8; d++) {
            o[d][0] *= alpha0; o[d][1] *= alpha0;
            o[d][2] *= alpha1; o[d][3] *= alpha1;
        }

#pragma unroll
        for (int ks = 0; ks < 4; ks++) {
            uint32_t pa_h[4], pa_l[4];
            pa_h[0] = pack_hi2(s[2 * ks][0], s[2 * ks][1]);
            pa_h[1] = pack_hi2(s[2 * ks][2], s[2 * ks][3]);
            pa_h[2] = pack_hi2(s[2 * ks + 1][0], s[2 * ks + 1][1]);
            pa_h[3] = pack_hi2(s[2 * ks + 1][2], s[2 * ks + 1][3]);
            pa_l[0] = pack_lo2(s[2 * ks][0], s[2 * ks][1]);
            pa_l[1] = pack_lo2(s[2 * ks][2], s[2 * ks][3]);
            pa_l[2] = pack_lo2(s[2 * ks + 1][0], s[2 * ks + 1][1]);
            pa_l[3] = pack_lo2(s[2 * ks + 1][2], s[2 * ks + 1][3]);
#pragma unroll
            for (int nb = 0; nb < 4; nb++) {
                uint32_t vh[4], vl[4];
                uint32_t offv = SW128((uint32_t)((ks * 16 + vkrow) * 128 + nb * 32 + vncol * 2));
                LDSM4T(vh[0], vh[1], vh[2], vh[3], kb + 16384 + offv);
                LDSM4T(vl[0], vl[1], vl[2], vl[3], kb + 24576 + offv);
#pragma unroll
                for (int niL = 0; niL < 2; niL++) {
                    int d = nb * 2 + niL, p = niL * 2;
                    MMA16816(o[d], pa_h, vh[p], vh[p + 1]);
                    MMA16816(o[d], pa_h, vl[p], vl[p + 1]);
                    MMA16816(o[d], pa_l, vh[p], vh[p + 1]);
                }
            }
        }
    }

    float inv0 = 1.0f / l0, inv1 = 1.0f / l1;
    size_t rb0 = ((size_t)b * SEQ + q0 + wid * 16 + (lane >> 2)) * DMODEL + h * DHEAD + (lane & 3) * 2;
    size_t rb1 = rb0 + 8 * DMODEL;
#pragma unroll
    for (int d = 0; d < 8; d++) {
        *(float2*)&z[rb0 + d * 8] = make_float2(to_tf32(o[d][0] * inv0), to_tf32(o[d][1] * inv0));
        *(float2*)&z[rb1 + d * 8] = make_float2(to_tf32(o[d][2] * inv1), to_tf32(o[d][3] * inv1));
    }
}

// ---------------- launch ----------------
extern "C" void kernel_launch(void* const* d_in, const int* in_sizes, int n_in,
                              void* d_out, int out_size) {
    const float* resid_pre = (const float*)d_in[0];
    const float* WQ  = (const float*)d_in[1];
    const float* WK  = (const float*)d_in[2];
    const float* WV  = (const float*)d_in[3];
    const float* WO  = (const float*)d_in[4];
    const float* bQ  = (const float*)d_in[5];
    const float* bK  = (const float*)d_in[6];
    const float* bV  = (const float*)d_in[7];
    const float* bO  = (const float*)d_in[8];
    const float* ln1w = (const float*)d_in[9];
    const float* ln1b = (const float*)d_in[10];
    const float* ln2w = (const float*)d_in[11];
    const float* ln2b = (const float*)d_in[12];
    const float* Win  = (const float*)d_in[13];
    const float* bin  = (const float*)d_in[14];
    const float* Wout = (const float*)d_in[15];
    const float* bout = (const float*)d_in[16];
    float* out = (float*)d_out;

    float *p_xn, *p_xn2, *p_z, *p_hid, *p_wqkv, *p_wo, *p_win, *p_wout, *p_bqkv, *p_mid;
    bf16 *p_qkvh, *p_qkvl;
    cudaGetSymbolAddress((void**)&p_xn, g_xn);
    cudaGetSymbolAddress((void**)&p_xn2, g_xn2);
    cudaGetSymbolAddress((void**)&p_z, g_z);
    cudaGetSymbolAddress((void**)&p_hid, g_hid);
    cudaGetSymbolAddress((void**)&p_qkvh, g_qkv_hi);
    cudaGetSymbolAddress((void**)&p_qkvl, g_qkv_lo);
    cudaGetSymbolAddress((void**)&p_wqkv, g_wqkv);
    cudaGetSymbolAddress((void**)&p_wo, g_wo);
    cudaGetSymbolAddress((void**)&p_win, g_win);
    cudaGetSymbolAddress((void**)&p_wout, g_wout);
    cudaGetSymbolAddress((void**)&p_bqkv, g_bqkv);
    cudaGetSymbolAddress((void**)&p_mid, g_mid);

    cudaFuncSetAttribute(attn_mma, cudaFuncAttributeMaxDynamicSharedMemorySize, ASMEM);
    cudaFuncSetAttribute(gemm_tf32<1>, cudaFuncAttributeMaxDynamicSharedMemorySize, TSMEM);
    cudaFuncSetAttribute(gemm_tf32<2>, cudaFuncAttributeMaxDynamicSharedMemorySize, TSMEM);
    cudaFuncSetAttribute(gemm_tf32<3>, cudaFuncAttributeMaxDynamicSharedMemorySize, TSMEM);

    // launch order fixed so ncu (-s 5 -c 1) captures attn_mma
    // 0) bias pack
    pack_bqkv_kernel<<<(QKVW + 255) / 256, 256>>>(bQ, bK, bV);
    // 1) QKV weight pack (merged, Q scaled 1/8)
    pack_qkvw<<<dim3(2, 24, 36), 256>>>(WQ, WK, WV);
    // 2) WO/Win/Wout pack (merged)
    pack_mlpw<<<5184, 256>>>(WO, Win, Wout);
    // 3) LN1 -> tf32 f32
    ln_kernel<<<MTOT, 256>>>(resid_pre, ln1w, ln1b, p_xn);
    // 4) QKV projection (tf32, 256x128 tiles) -> bf16 hi/lo
    gemm_tf32<3><<<dim3(QKVW / 128, MTOT / 256), 512, TSMEM>>>(
        p_xn, p_wqkv, p_bqkv, nullptr, nullptr, p_qkvh, p_qkvl, QKVW, DMODEL, DMODEL / 32);
    // 5) causal flash attention  <-- ncu capture lands here
    attn_mma<<<dim3(SEQ / 128, NHEADS, BATCH), 256, ASMEM>>>(p_qkvh, p_qkvl, p_z);
    // 6) O projection + residual
    gemm_tf32<2><<<dim3(DMODEL / 128, MTOT / 256), 512, TSMEM>>>(
        p_z, p_wo, bO, resid_pre, p_mid, nullptr, nullptr, DMODEL, DMODEL, DMODEL / 32);
    // 7) LN2
    ln_kernel<<<MTOT, 256>>>(p_mid, ln2w, ln2b, p_xn2);
    // 8) MLP in + GELU
    gemm_tf32<1><<<dim3(DMLP / 128, MTOT / 256), 512, TSMEM>>>(
        p_xn2, p_win, bin, nullptr, p_hid, nullptr, nullptr, DMLP, DMODEL, DMODEL / 32);
    // 9) MLP out + residual
    gemm_tf32<2><<<dim3(DMODEL / 128, MTOT / 256), 512, TSMEM>>>(
        p_hid, p_wout, bout, p_mid, out, nullptr, nullptr, DMODEL, DMLP, DMLP / 32);
}

// round 10
// speedup vs baseline: 1.1426x; 1.1426x over previous
#include <cuda_runtime.h>
#include <cuda_bf16.h>
#include <math.h>
#include <stdint.h>

#define MTOT   8192
#define DMODEL 768
#define NHEADS 12
#define DHEAD  64
#define DMLP   3072
#define SEQ    1024
#define BATCH  8
#define QKVW   (3*DMODEL)

typedef __nv_bfloat16 bf16;

// ---------------- scratch ----------------
__device__ __align__(256) float g_xn [MTOT*DMODEL];
__device__ __align__(256) float g_xn2[MTOT*DMODEL];
__device__ __align__(256) float g_z  [MTOT*DMODEL];
__device__ __align__(256) float g_hid[(size_t)MTOT*DMLP];
__device__ __align__(256) bf16 g_qkv_hi[(size_t)MTOT*QKVW];
__device__ __align__(256) bf16 g_qkv_lo[(size_t)MTOT*QKVW];
__device__ __align__(256) float g_wqkv[QKVW*DMODEL];
__device__ __align__(256) float g_wo  [DMODEL*DMODEL];
__device__ __align__(256) float g_win [DMODEL*DMLP];
__device__ __align__(256) float g_wout[DMLP*DMODEL];
__device__ float g_bqkv[QKVW];
__device__ float g_mid [MTOT*DMODEL];

// ---------------- helpers ----------------
__device__ __forceinline__ uint32_t smem_u32(const void* p) {
    uint32_t a;
    asm("{ .reg .u64 t; cvta.to.shared.u64 t, %1; cvt.u32.u64 %0, t; }" : "=r"(a) : "l"(p));
    return a;
}
#define SW128(o) ((o) ^ (((o) >> 3) & 0x70))

__device__ __forceinline__ void cp16(uint32_t dst, const void* src) {
    asm volatile("cp.async.cg.shared.global [%0], [%1], 16;" :: "r"(dst), "l"(src));
}
#define CP_COMMIT() asm volatile("cp.async.commit_group;" ::: "memory")
#define CP_WAIT(n)  asm volatile("cp.async.wait_group %0;" :: "n"(n) : "memory")

#define LDSM4(r0, r1, r2, r3, addr) \
    asm volatile("ldmatrix.sync.aligned.m8n8.x4.shared.b16 {%0,%1,%2,%3},[%4];" \
        : "=r"(r0), "=r"(r1), "=r"(r2), "=r"(r3) : "r"(addr))
#define LDSM4T(r0, r1, r2, r3, addr) \
    asm volatile("ldmatrix.sync.aligned.m8n8.x4.trans.shared.b16 {%0,%1,%2,%3},[%4];" \
        : "=r"(r0), "=r"(r1), "=r"(r2), "=r"(r3) : "r"(addr))

#define MMA16816(d, a, b0, b1) \
    asm volatile("mma.sync.aligned.m16n8k16.row.col.f32.bf16.bf16.f32 " \
        "{%0,%1,%2,%3},{%4,%5,%6,%7},{%8,%9},{%0,%1,%2,%3};" \
        : "+f"((d)[0]), "+f"((d)[1]), "+f"((d)[2]), "+f"((d)[3]) \
        : "r"((a)[0]), "r"((a)[1]), "r"((a)[2]), "r"((a)[3]), "r"(b0), "r"(b1))

#define MMATF32(d, a, b0, b1) \
    asm volatile("mma.sync.aligned.m16n8k8.row.col.f32.tf32.tf32.f32 " \
        "{%0,%1,%2,%3},{%4,%5,%6,%7},{%8,%9},{%0,%1,%2,%3};" \
        : "+f"((d)[0]), "+f"((d)[1]), "+f"((d)[2]), "+f"((d)[3]) \
        : "r"((a)[0]), "r"((a)[1]), "r"((a)[2]), "r"((a)[3]), "r"(b0), "r"(b1))

__device__ __forceinline__ float to_tf32(float x) {
    uint32_t u;
    asm("cvt.rna.tf32.f32 %0, %1;" : "=r"(u) : "f"(x));
    return __uint_as_float(u);
}
__device__ __forceinline__ float gelu_new_f(float x) {
    float x3 = x * x * x;
    return 0.5f * x * (1.0f + tanhf(0.7978845608028654f * (x + 0.044715f * x3)));
}
__device__ __forceinline__ uint32_t pack_bf162(bf16 a, bf16 b) {
    __nv_bfloat162 t(a, b);
    return *(uint32_t*)&t;
}
__device__ __forceinline__ uint32_t pack_hi2(float a, float b) {
    return pack_bf162(__float2bfloat16(a), __float2bfloat16(b));
}
__device__ __forceinline__ uint32_t pack_lo2(float a, float b) {
    bf16 ha = __float2bfloat16(a), hb = __float2bfloat16(b);
    return pack_bf162(__float2bfloat16(a - __bfloat162float(ha)),
                      __float2bfloat16(b - __bfloat162float(hb)));
}

// ---------------- packs ----------------
__global__ void pack_bqkv_kernel(const float* __restrict__ bQ, const float* __restrict__ bK,
                                 const float* __restrict__ bV) {
    int i = threadIdx.x + blockIdx.x * 256;
    if (i >= QKVW) return;
    g_bqkv[i] = (i < DMODEL) ? bQ[i] * 0.125f : (i < 2 * DMODEL ? bK[i - DMODEL] : bV[i - 2 * DMODEL]);
}

// W_{Q,K,V}[h][d][e] -> g_wqkv[(sel*768 + h*64 + e)][d], Q scaled 1/8
__global__ __launch_bounds__(256)
void pack_qkvw(const float* __restrict__ WQ, const float* __restrict__ WK,
               const float* __restrict__ WV) {
    __shared__ float t[32][33];
    int z = blockIdx.z;
    int sel = z / NHEADS, h = z % NHEADS;
    const float* src = (sel == 0 ? WQ : sel == 1 ? WK : WV) + (size_t)h * DMODEL * DHEAD;
    float scale = sel == 0 ? 0.125f : 1.0f;
    int r0 = blockIdx.y * 32, c0 = blockIdx.x * 32;
    int tr = threadIdx.x >> 5, tc = threadIdx.x & 31;
#pragma unroll
    for (int i = 0; i < 4; i++)
        t[tr + i * 8][tc] = src[(size_t)(r0 + tr + i * 8) * DHEAD + c0 + tc];
    __syncthreads();
    int colbase = sel * DMODEL + h * DHEAD + c0;
#pragma unroll
    for (int i = 0; i < 4; i++) {
        int cc = tr + i * 8;
        g_wqkv[(size_t)(colbase + cc) * DMODEL + r0 + tc] = to_tf32(t[tc][cc] * scale);
    }
}

// WO/Win/Wout transposes in one launch (flat 32x32 tile index)
__global__ __launch_bounds__(256)
void pack_mlpw(const float* __restrict__ WO, const float* __restrict__ Win,
               const float* __restrict__ Wout) {
    __shared__ float t[32][33];
    int ti = blockIdx.x;
    const float* src; float* dst; int R, C, rt, ct;
    if (ti < 576)        { src = WO;   dst = g_wo;   R = DMODEL; C = DMODEL; rt = ti / 24;  ct = ti % 24; }
    else if (ti < 2880)  { int u = ti - 576;  src = Win;  dst = g_win;  R = DMODEL; C = DMLP;   rt = u / 96; ct = u % 96; }
    else                 { int u = ti - 2880; src = Wout; dst = g_wout; R = DMLP;   C = DMODEL; rt = u / 24; ct = u % 24; }
    int r0 = rt * 32, c0 = ct * 32;
    int tr = threadIdx.x >> 5, tc = threadIdx.x & 31;
#pragma unroll
    for (int i = 0; i < 4; i++)
        t[tr + i * 8][tc] = src[(size_t)(r0 + tr + i * 8) * C + c0 + tc];
    __syncthreads();
#pragma unroll
    for (int i = 0; i < 4; i++) {
        int cc = tr + i * 8;
        dst[(size_t)(c0 + cc) * R + r0 + tc] = to_tf32(t[tc][cc]);
    }
}

// ---------------- layernorm -> tf32-rounded f32 ----------------
__global__ __launch_bounds__(256)
void ln_kernel(const float* __restrict__ x, const float* __restrict__ w, const float* __restrict__ b,
               float* __restrict__ y) {
    __shared__ float ws[8], wq[8], stats[2];
    int row = blockIdx.x, tid = threadIdx.x;
    const float* xr = x + (size_t)row * DMODEL;
    float v0 = xr[tid], v1 = xr[tid + 256], v2 = xr[tid + 512];
    float s = v0 + v1 + v2, sq = v0 * v0 + v1 * v1 + v2 * v2;
#pragma unroll
    for (int o = 16; o > 0; o >>= 1) {
        s  += __shfl_xor_sync(0xffffffffu, s,  o);
        sq += __shfl_xor_sync(0xffffffffu, sq, o);
    }
    if ((tid & 31) == 0) { ws[tid >> 5] = s; wq[tid >> 5] = sq; }
    __syncthreads();
    if (tid == 0) {
        float ts = 0.f, tq = 0.f;
#pragma unroll
        for (int i = 0; i < 8; i++) { ts += ws[i]; tq += wq[i]; }
        float mean = ts * (1.0f / DMODEL);
        float var  = tq * (1.0f / DMODEL) - mean * mean;
        stats[0] = mean; stats[1] = rsqrtf(var + 1e-5f);
    }
    __syncthreads();
    float mean = stats[0], rstd = stats[1];
    size_t base = (size_t)row * DMODEL;
#pragma unroll
    for (int u = 0; u < 3; u++) {
        int c = tid + u * 256;
        float yv = ((u == 0 ? v0 : u == 1 ? v1 : v2) - mean) * rstd * w[c] + b[c];
        y[base + c] = to_tf32(yv);
    }
}

// ---------------- TF32 GEMM: C[M,N] = A[M,K] * B[N,K]^T ----------------
// 128x128 CTA tile, KC=32, 3-stage cp.async, 8 warps (2x4), 64x32 warp tile, 2 CTA/SM.
// EPI: 1 = bias+gelu->tf32 f32 ; 2 = bias+resid->f32 ; 3 = bias->bf16 hi/lo
#define TTILE 16384
#define TSTG  (2*TTILE)
#define TSMEM (1024 + 3*TSTG)

__device__ __forceinline__ void stage_tf(uint32_t tb, const float* A, const float* B,
                                         int k0, int K, int tid) {
#pragma unroll
    for (int it = 0; it < 4; it++) {
        int idx = tid + it * 256;
        int row = idx >> 3, seg = idx & 7;
        uint32_t off = SW128((uint32_t)(row * 128 + seg * 16));
        cp16(tb + off,         A + (size_t)row * K + k0 + seg * 4);
        cp16(tb + TTILE + off, B + (size_t)row * K + k0 + seg * 4);
    }
    CP_COMMIT();
}

template <int EPI>
__global__ __launch_bounds__(256, 2)
void gemm_tf32(const float* __restrict__ A, const float* __restrict__ B,
               const float* __restrict__ bias, const float* __restrict__ R,
               float* __restrict__ C, bf16* __restrict__ Chi, bf16* __restrict__ Clo,
               int N, int K, int NC) {
    extern __shared__ char smraw[];
    uint32_t sb = (smem_u32(smraw) + 1023) & ~1023u;
    int tid = threadIdx.x;
    int row0 = blockIdx.y * 128, col0 = blockIdx.x * 128;
    int wid = tid >> 5, lane = tid & 31;
    int wm = (wid >> 2) * 64, wn = (wid & 3) * 32;

    const float* Ab = A + (size_t)row0 * K;
    const float* Bb = B + (size_t)col0 * K;

    stage_tf(sb,        Ab, Bb, 0,  K, tid);
    stage_tf(sb + TSTG, Ab, Bb, 32, K, tid);

    float acc[4][4][4];
#pragma unroll
    for (int mi = 0; mi < 4; mi++)
#pragma unroll
        for (int ni = 0; ni < 4; ni++)
#pragma unroll
            for (int q = 0; q < 4; q++) acc[mi][ni][q] = 0.f;

    int ar = lane & 15, acol = (lane >> 4) * 16;
    int brt = (lane & 7) + ((lane >> 4) & 1) * 8;
    int bct = ((lane >> 3) & 1) * 16;

    for (int i = 0; i < NC; i++) {
        if (i + 2 < NC) {
            stage_tf(sb + (uint32_t)((i + 2) % 3) * TSTG, Ab, Bb, (i + 2) * 32, K, tid);
            CP_WAIT(2);
        } else {
            CP_WAIT(0);
        }
        __syncthreads();
        uint32_t tb = sb + (uint32_t)(i % 3) * TSTG;
#pragma unroll
        for (int ks = 0; ks < 4; ks++) {
            uint32_t af[4][4], bfr[2][4];
#pragma unroll
            for (int mi = 0; mi < 4; mi++) {
                uint32_t off = SW128((uint32_t)((wm + mi * 16 + ar) * 128 + ks * 32 + acol));
                LDSM4(af[mi][0], af[mi][1], af[mi][2], af[mi][3], tb + off);
            }
#pragma unroll
            for (int nb = 0; nb < 2; nb++) {
                uint32_t off = SW128((uint32_t)((wn + nb * 16 + brt) * 128 + ks * 32 + bct));
                LDSM4(bfr[nb][0], bfr[nb][1], bfr[nb][2], bfr[nb][3], tb + TTILE + off);
            }
#pragma unroll
            for (int mi = 0; mi < 4; mi++)
#pragma unroll
                for (int ni = 0; ni < 4; ni++) {
                    int nb = ni >> 1, p = (ni & 1) * 2;
                    MMATF32(acc[mi][ni], af[mi], bfr[nb][p], bfr[nb][p + 1]);
                }
        }
        __syncthreads();
    }

#pragma unroll
    for (int mi = 0; mi < 4; mi++) {
#pragma unroll
        for (int ni = 0; ni < 4; ni++) {
            int r = row0 + wm + mi * 16 + (lane >> 2);
            int c = col0 + wn + ni * 8 + (lane & 3) * 2;
            float b0 = bias[c], b1 = bias[c + 1];
#pragma unroll
            for (int half = 0; half < 2; half++) {
                int rr = r + half * 8;
                float v0 = acc[mi][ni][2 * half]     + b0;
                float v1 = acc[mi][ni][2 * half + 1] + b1;
                if (EPI == 1) {
                    *(float2*)&C[(size_t)rr * N + c] =
                        make_float2(to_tf32(gelu_new_f(v0)), to_tf32(gelu_new_f(v1)));
                } else if (EPI == 3) {
                    *(uint32_t*)&Chi[(size_t)rr * N + c] = pack_hi2(v0, v1);
                    *(uint32_t*)&Clo[(size_t)rr * N + c] = pack_lo2(v0, v1);
                } else {
                    float2 rv = *(const float2*)&R[(size_t)rr * N + c];
                    *(float2*)&C[(size_t)rr * N + c] = make_float2(v0 + rv.x, v1 + rv.y);
                }
            }
        }
    }
}

// ---------------- mma flash attention, split-bf16 ----------------
#define ASTG0 32768
#define ASTG  32768
#define ASMEM (1024 + ASTG0 + 2*ASTG)
#define NEGINF (-1e30f)

__device__ __forceinline__ void attn_stage_kv(uint32_t kb, const bf16* kh, const bf16* kl,
                                              const bf16* vh, const bf16* vl, int tid) {
#pragma unroll
    for (int it = 0; it < 2; it++) {
        int idx = tid + it * 256;
        int row = idx >> 3, seg = idx & 7;
        uint32_t off = SW128((uint32_t)(row * 128 + seg * 16));
        size_t g = (size_t)row * QKVW + seg * 8;
        cp16(kb + off,         kh + g);
        cp16(kb + 8192 + off,  kl + g);
        cp16(kb + 16384 + off, vh + g);
        cp16(kb + 24576 + off, vl + g);
    }
}

__global__ __launch_bounds__(256, 2)
void attn_mma(const bf16* __restrict__ qkvh, const bf16* __restrict__ qkvl,
              float* __restrict__ z) {
    extern __shared__ char smraw[];
    uint32_t sq = (smem_u32(smraw) + 1023) & ~1023u;
    uint32_t sstage = sq + ASTG0;
    int tid = threadIdx.x, wid = tid >> 5, lane = tid & 31;
    int qt = blockIdx.x, h = blockIdx.y, b = blockIdx.z;
    int q0 = qt * 128;
    size_t tokbase = (size_t)b * SEQ * QKVW;
    const bf16* qhp = qkvh + tokbase + (size_t)q0 * QKVW + h * DHEAD;
    const bf16* qlp = qkvl + tokbase + (size_t)q0 * QKVW + h * DHEAD;
    const bf16* khp = qkvh + tokbase + DMODEL + h * DHEAD;
    const bf16* klp = qkvl + tokbase + DMODEL + h * DHEAD;
    const bf16* vhp = qkvh + tokbase + 2 * DMODEL + h * DHEAD;
    const bf16* vlp = qkvl + tokbase + 2 * DMODEL + h * DHEAD;

#pragma unroll
    for (int it = 0; it < 4; it++) {
        int idx = tid + it * 256;
        int row = idx >> 3, seg = idx & 7;
        uint32_t off = SW128((uint32_t)(row * 128 + seg * 16));
        size_t g = (size_t)row * QKVW + seg * 8;
        cp16(sq + off,         qhp + g);
        cp16(sq + 16384 + off, qlp + g);
    }
    CP_COMMIT();
    attn_stage_kv(sstage, khp, klp, vhp, vlp, tid);
    CP_COMMIT();

    float o[8][4];
#pragma unroll
    for (int d = 0; d < 8; d++)
#pragma unroll
        for (int q = 0; q < 4; q++) o[d][q] = 0.f;
    float m0 = NEGINF, m1 = NEGINF, l0 = 0.f, l1 = 0.f;

    int ar = lane & 15, ahalf = lane >> 4;
    int brow = (lane & 7) + ((lane >> 4) << 3);
    int bhalf = (lane >> 3) & 1;
    int vkrow = (lane & 7) + (((lane >> 3) & 1) << 3);
    int vncol = (lane >> 4) * 8;
    int r0g = q0 + wid * 16 + (lane >> 2);

    int nkt = 2 * qt + 2;
    for (int kt = 0; kt < nkt; kt++) {
        __syncthreads();
        if (kt + 1 < nkt) {
            attn_stage_kv(sstage + (uint32_t)((kt + 1) & 1) * ASTG,
                          khp + (size_t)(kt + 1) * 64 * QKVW, klp + (size_t)(kt + 1) * 64 * QKVW,
                          vhp + (size_t)(kt + 1) * 64 * QKVW, vlp + (size_t)(kt + 1) * 64 * QKVW, tid);
            CP_COMMIT();
            CP_WAIT(1);
        } else {
            CP_WAIT(0);
        }
        __syncthreads();
        uint32_t kb = sstage + (uint32_t)(kt & 1) * ASTG;

        float s[8][4];
#pragma unroll
        for (int ni = 0; ni < 8; ni++)
#pragma unroll
            for (int q = 0; q < 4; q++) s[ni][q] = 0.f;
#pragma unroll
        for (int ks = 0; ks < 4; ks++) {
            uint32_t ah[4], al[4];
            uint32_t offa = SW128((uint32_t)((wid * 16 + ar) * 128 + ks * 32 + ahalf * 16));
            LDSM4(ah[0], ah[1], ah[2], ah[3], sq + offa);
            LDSM4(al[0], al[1], al[2], al[3], sq + 16384 + offa);
#pragma unroll
            for (int nb = 0; nb < 4; nb++) {
                uint32_t bh[4], bl[4];
                uint32_t offb = SW128((uint32_t)((nb * 16 + brow) * 128 + ks * 32 + bhalf * 16));
                LDSM4(bh[0], bh[1], bh[2], bh[3], kb + offb);
                LDSM4(bl[0], bl[1], bl[2], bl[3], kb + 8192 + offb);
#pragma unroll
                for (int niL = 0; niL < 2; niL++) {
                    int ni = nb * 2 + niL, p = niL * 2;
                    MMA16816(s[ni], ah, bh[p], bh[p + 1]);
                    MMA16816(s[ni], ah, bl[p], bl[p + 1]);
                    MMA16816(s[ni], al, bh[p], bh[p + 1]);
                }
            }
        }

        if (kt >= 2 * qt) {
            int cbase = kt * 64 + (lane & 3) * 2;
#pragma unroll
            for (int ni = 0; ni < 8; ni++) {
                int c0 = cbase + ni * 8, c1 = c0 + 1;
                if (c0 > r0g)     s[ni][0] = NEGINF;
                if (c1 > r0g)     s[ni][1] = NEGINF;
                if (c0 > r0g + 8) s[ni][2] = NEGINF;
                if (c1 > r0g + 8) s[ni][3] = NEGINF;
            }
        }

        float tm0 = NEGINF, tm1 = NEGINF;
#pragma unroll
        for (int ni = 0; ni < 8; ni++) {
            tm0 = fmaxf(tm0, fmaxf(s[ni][0], s[ni][1]));
            tm1 = fmaxf(tm1, fmaxf(s[ni][2], s[ni][3]));
        }
        tm0 = fmaxf(tm0, __shfl_xor_sync(0xffffffffu, tm0, 1));
        tm0 = fmaxf(tm0, __shfl_xor_sync(0xffffffffu, tm0, 2));
        tm1 = fmaxf(tm1, __shfl_xor_sync(0xffffffffu, tm1, 1));
        tm1 = fmaxf(tm1, __shfl_xor_sync(0xffffffffu, tm1, 2));
        float nm0 = fmaxf(m0, tm0), nm1 = fmaxf(m1, tm1);
        float alpha0 = __expf(m0 - nm0), alpha1 = __expf(m1 - nm1);
        m0 = nm0; m1 = nm1;
        float rs0 = 0.f, rs1 = 0.f;
#pragma unroll
        for (int ni = 0; ni < 8; ni++) {
            s[ni][0] = __expf(s[ni][0] - nm0);
            s[ni][1] = __expf(s[ni][1] - nm0);
            s[ni][2] = __expf(s[ni][2] - nm1);
            s[ni][3] = __expf(s[ni][3] - nm1);
            rs0 += s[ni][0] + s[ni][1];
            rs1 += s[ni][2] + s[ni][3];
        }
        rs0 += __shfl_xor_sync(0xffffffffu, rs0, 1);
        rs0 += __shfl_xor_sync(0xffffffffu, rs0, 2);
        rs1 += __shfl_xor_sync(0xffffffffu, rs1, 1);
        rs1 += __shfl_xor_sync(0xffffffffu, rs1, 2);
        l0 = l0 * alpha0 + rs0;
        l1 = l1 * alpha1 + rs1;
#pragma unroll
        for (int d = 0; d < 8; d++) {
            o[d][0] *= alpha0; o[d][1] *= alpha0;
            o[d][2] *= alpha1; o[d][3] *= alpha1;
        }

#pragma unroll
        for (int ks = 0; ks < 4; ks++) {
            uint32_t pa_h[4], pa_l[4];
            pa_h[0] = pack_hi2(s[2 * ks][0], s[2 * ks][1]);
            pa_h[1] = pack_hi2(s[2 * ks][2], s[2 * ks][3]);
            pa_h[2] = pack_hi2(s[2 * ks + 1][0], s[2 * ks + 1][1]);
            pa_h[3] = pack_hi2(s[2 * ks + 1][2], s[2 * ks + 1][3]);
            pa_l[0] = pack_lo2(s[2 * ks][0], s[2 * ks][1]);
            pa_l[1] = pack_lo2(s[2 * ks][2], s[2 * ks][3]);
            pa_l[2] = pack_lo2(s[2 * ks + 1][0], s[2 * ks + 1][1]);
            pa_l[3] = pack_lo2(s[2 * ks + 1][2], s[2 * ks + 1][3]);
#pragma unroll
            for (int nb = 0; nb < 4; nb++) {
                uint32_t vh[4], vl[4];
                uint32_t offv = SW128((uint32_t)((ks * 16 + vkrow) * 128 + nb * 32 + vncol * 2));
                LDSM4T(vh[0], vh[1], vh[2], vh[3], kb + 16384 + offv);
                LDSM4T(vl[0], vl[1], vl[2], vl[3], kb + 24576 + offv);
#pragma unroll
                for (int niL = 0; niL < 2; niL++) {
                    int d = nb * 2 + niL, p = niL * 2;
                    MMA16816(o[d], pa_h, vh[p], vh[p + 1]);
                    MMA16816(o[d], pa_h, vl[p], vl[p + 1]);
                    MMA16816(o[d], pa_l, vh[p], vh[p + 1]);
                }
            }
        }
    }

    float inv0 = 1.0f / l0, inv1 = 1.0f / l1;
    size_t rb0 = ((size_t)b * SEQ + q0 + wid * 16 + (lane >> 2)) * DMODEL + h * DHEAD + (lane & 3) * 2;
    size_t rb1 = rb0 + 8 * DMODEL;
#pragma unroll
    for (int d = 0; d < 8; d++) {
        *(float2*)&z[rb0 + d * 8] = make_float2(to_tf32(o[d][0] * inv0), to_tf32(o[d][1] * inv0));
        *(float2*)&z[rb1 + d * 8] = make_float2(to_tf32(o[d][2] * inv1), to_tf32(o[d][3] * inv1));
    }
}

// ---------------- launch ----------------
extern "C" void kernel_launch(void* const* d_in, const int* in_sizes, int n_in,
                              void* d_out, int out_size) {
    const float* resid_pre = (const float*)d_in[0];
    const float* WQ  = (const float*)d_in[1];
    const float* WK  = (const float*)d_in[2];
    const float* WV  = (const float*)d_in[3];
    const float* WO  = (const float*)d_in[4];
    const float* bQ  = (const float*)d_in[5];
    const float* bK  = (const float*)d_in[6];
    const float* bV  = (const float*)d_in[7];
    const float* bO  = (const float*)d_in[8];
    const float* ln1w = (const float*)d_in[9];
    const float* ln1b = (const float*)d_in[10];
    const float* ln2w = (const float*)d_in[11];
    const float* ln2b = (const float*)d_in[12];
    const float* Win  = (const float*)d_in[13];
    const float* bin  = (const float*)d_in[14];
    const float* Wout = (const float*)d_in[15];
    const float* bout = (const float*)d_in[16];
    float* out = (float*)d_out;

    float *p_xn, *p_xn2, *p_z, *p_hid, *p_wqkv, *p_wo, *p_win, *p_wout, *p_bqkv, *p_mid;
    bf16 *p_qkvh, *p_qkvl;
    cudaGetSymbolAddress((void**)&p_xn, g_xn);
    cudaGetSymbolAddress((void**)&p_xn2, g_xn2);
    cudaGetSymbolAddress((void**)&p_z, g_z);
    cudaGetSymbolAddress((void**)&p_hid, g_hid);
    cudaGetSymbolAddress((void**)&p_qkvh, g_qkv_hi);
    cudaGetSymbolAddress((void**)&p_qkvl, g_qkv_lo);
    cudaGetSymbolAddress((void**)&p_wqkv, g_wqkv);
    cudaGetSymbolAddress((void**)&p_wo, g_wo);
    cudaGetSymbolAddress((void**)&p_win, g_win);
    cudaGetSymbolAddress((void**)&p_wout, g_wout);
    cudaGetSymbolAddress((void**)&p_bqkv, g_bqkv);
    cudaGetSymbolAddress((void**)&p_mid, g_mid);

    cudaFuncSetAttribute(attn_mma, cudaFuncAttributeMaxDynamicSharedMemorySize, ASMEM);
    cudaFuncSetAttribute(gemm_tf32<1>, cudaFuncAttributeMaxDynamicSharedMemorySize, TSMEM);
    cudaFuncSetAttribute(gemm_tf32<2>, cudaFuncAttributeMaxDynamicSharedMemorySize, TSMEM);
    cudaFuncSetAttribute(gemm_tf32<3>, cudaFuncAttributeMaxDynamicSharedMemorySize, TSMEM);

    // 0) bias pack
    pack_bqkv_kernel<<<(QKVW + 255) / 256, 256>>>(bQ, bK, bV);
    // 1) QKV weight pack (merged, Q scaled 1/8)
    pack_qkvw<<<dim3(2, 24, 36), 256>>>(WQ, WK, WV);
    // 2) WO/Win/Wout pack (merged)
    pack_mlpw<<<5184, 256>>>(WO, Win, Wout);
    // 3) LN1 -> tf32 f32
    ln_kernel<<<MTOT, 256>>>(resid_pre, ln1w, ln1b, p_xn);
    // 4) QKV projection (tf32, 128x128 tiles, 2 CTA/SM) -> bf16 hi/lo
    gemm_tf32<3><<<dim3(QKVW / 128, MTOT / 128), 256, TSMEM>>>(
        p_xn, p_wqkv, p_bqkv, nullptr, nullptr, p_qkvh, p_qkvl, QKVW, DMODEL, DMODEL / 32);
    // 5) causal flash attention
    attn_mma<<<dim3(SEQ / 128, NHEADS, BATCH), 256, ASMEM>>>(p_qkvh, p_qkvl, p_z);
    // 6) O projection + residual
    gemm_tf32<2><<<dim3(DMODEL / 128, MTOT / 128), 256, TSMEM>>>(
        p_z, p_wo, bO, resid_pre, p_mid, nullptr, nullptr, DMODEL, DMODEL, DMODEL / 32);
    // 7) LN2
    ln_kernel<<<MTOT, 256>>>(p_mid, ln2w, ln2b, p_xn2);
    // 8) MLP in + GELU
    gemm_tf32<1><<<dim3(DMLP / 128, MTOT / 128), 256, TSMEM>>>(
        p_xn2, p_win, bin, nullptr, p_hid, nullptr, nullptr, DMLP, DMODEL, DMODEL / 32);
    // 9) MLP out + residual
    gemm_tf32<2><<<dim3(DMODEL / 128, MTOT / 128), 256, TSMEM>>>(
        p_hid, p_wout, bout, p_mid, out, nullptr, nullptr, DMODEL, DMLP, DMLP / 32);
}

// round 11
// speedup vs baseline: 1.1969x; 1.0476x over previous
#include <cuda_runtime.h>
#include <cuda_bf16.h>
#include <math.h>
#include <stdint.h>

#define MTOT   8192
#define DMODEL 768
#define NHEADS 12
#define DHEAD  64
#define DMLP   3072
#define SEQ    1024
#define BATCH  8
#define QKVW   (3*DMODEL)

typedef __nv_bfloat16 bf16;

// ---------------- scratch ----------------
__device__ __align__(256) float g_xn [MTOT*DMODEL];
__device__ __align__(256) float g_xn2[MTOT*DMODEL];
__device__ __align__(256) float g_z  [MTOT*DMODEL];
__device__ __align__(256) float g_hid[(size_t)MTOT*DMLP];
__device__ __align__(256) bf16 g_qkv_hi[(size_t)MTOT*QKVW];
__device__ __align__(256) bf16 g_qkv_lo[(size_t)MTOT*QKVW];
__device__ __align__(256) float g_wqkv[QKVW*DMODEL];
__device__ __align__(256) float g_wo  [DMODEL*DMODEL];
__device__ __align__(256) float g_win [DMODEL*DMLP];
__device__ __align__(256) float g_wout[DMLP*DMODEL];
__device__ float g_bqkv[QKVW];
__device__ float g_mid [MTOT*DMODEL];

// ---------------- helpers ----------------
__device__ __forceinline__ uint32_t smem_u32(const void* p) {
    uint32_t a;
    asm("{ .reg .u64 t; cvta.to.shared.u64 t, %1; cvt.u32.u64 %0, t; }" : "=r"(a) : "l"(p));
    return a;
}
#define SW128(o) ((o) ^ (((o) >> 3) & 0x70))

__device__ __forceinline__ void cp16(uint32_t dst, const void* src) {
    asm volatile("cp.async.cg.shared.global [%0], [%1], 16;" :: "r"(dst), "l"(src));
}
#define CP_COMMIT() asm volatile("cp.async.commit_group;" ::: "memory")
#define CP_WAIT(n)  asm volatile("cp.async.wait_group %0;" :: "n"(n) : "memory")

#define LDSM4(r0, r1, r2, r3, addr) \
    asm volatile("ldmatrix.sync.aligned.m8n8.x4.shared.b16 {%0,%1,%2,%3},[%4];" \
        : "=r"(r0), "=r"(r1), "=r"(r2), "=r"(r3) : "r"(addr))
#define LDSM4T(r0, r1, r2, r3, addr) \
    asm volatile("ldmatrix.sync.aligned.m8n8.x4.trans.shared.b16 {%0,%1,%2,%3},[%4];" \
        : "=r"(r0), "=r"(r1), "=r"(r2), "=r"(r3) : "r"(addr))

#define MMA16816(d, a, b0, b1) \
    asm volatile("mma.sync.aligned.m16n8k16.row.col.f32.bf16.bf16.f32 " \
        "{%0,%1,%2,%3},{%4,%5,%6,%7},{%8,%9},{%0,%1,%2,%3};" \
        : "+f"((d)[0]), "+f"((d)[1]), "+f"((d)[2]), "+f"((d)[3]) \
        : "r"((a)[0]), "r"((a)[1]), "r"((a)[2]), "r"((a)[3]), "r"(b0), "r"(b1))

#define MMATF32(d, a, b0, b1) \
    asm volatile("mma.sync.aligned.m16n8k8.row.col.f32.tf32.tf32.f32 " \
        "{%0,%1,%2,%3},{%4,%5,%6,%7},{%8,%9},{%0,%1,%2,%3};" \
        : "+f"((d)[0]), "+f"((d)[1]), "+f"((d)[2]), "+f"((d)[3]) \
        : "r"((a)[0]), "r"((a)[1]), "r"((a)[2]), "r"((a)[3]), "r"(b0), "r"(b1))

__device__ __forceinline__ float to_tf32(float x) {
    uint32_t u;
    asm("cvt.rna.tf32.f32 %0, %1;" : "=r"(u) : "f"(x));
    return __uint_as_float(u);
}
__device__ __forceinline__ float gelu_new_f(float x) {
    float x3 = x * x * x;
    return 0.5f * x * (1.0f + tanhf(0.7978845608028654f * (x + 0.044715f * x3)));
}
__device__ __forceinline__ uint32_t pack_bf162(bf16 a, bf16 b) {
    __nv_bfloat162 t(a, b);
    return *(uint32_t*)&t;
}
__device__ __forceinline__ uint32_t pack_hi2(float a, float b) {
    return pack_bf162(__float2bfloat16(a), __float2bfloat16(b));
}
__device__ __forceinline__ uint32_t pack_lo2(float a, float b) {
    bf16 ha = __float2bfloat16(a), hb = __float2bfloat16(b);
    return pack_bf162(__float2bfloat16(a - __bfloat162float(ha)),
                      __float2bfloat16(b - __bfloat162float(hb)));
}

// ---------------- packs ----------------
__global__ void pack_bqkv_kernel(const float* __restrict__ bQ, const float* __restrict__ bK,
                                 const float* __restrict__ bV) {
    int i = threadIdx.x + blockIdx.x * 256;
    if (i >= QKVW) return;
    g_bqkv[i] = (i < DMODEL) ? bQ[i] * 0.125f : (i < 2 * DMODEL ? bK[i - DMODEL] : bV[i - 2 * DMODEL]);
}

__global__ __launch_bounds__(256)
void pack_qkvw(const float* __restrict__ WQ, const float* __restrict__ WK,
               const float* __restrict__ WV) {
    __shared__ float t[32][33];
    int z = blockIdx.z;
    int sel = z / NHEADS, h = z % NHEADS;
    const float* src = (sel == 0 ? WQ : sel == 1 ? WK : WV) + (size_t)h * DMODEL * DHEAD;
    float scale = sel == 0 ? 0.125f : 1.0f;
    int r0 = blockIdx.y * 32, c0 = blockIdx.x * 32;
    int tr = threadIdx.x >> 5, tc = threadIdx.x & 31;
#pragma unroll
    for (int i = 0; i < 4; i++)
        t[tr + i * 8][tc] = src[(size_t)(r0 + tr + i * 8) * DHEAD + c0 + tc];
    __syncthreads();
    int colbase = sel * DMODEL + h * DHEAD + c0;
#pragma unroll
    for (int i = 0; i < 4; i++) {
        int cc = tr + i * 8;
        g_wqkv[(size_t)(colbase + cc) * DMODEL + r0 + tc] = to_tf32(t[tc][cc] * scale);
    }
}

__global__ __launch_bounds__(256)
void pack_mlpw(const float* __restrict__ WO, const float* __restrict__ Win,
               const float* __restrict__ Wout) {
    __shared__ float t[32][33];
    int ti = blockIdx.x;
    const float* src; float* dst; int R, C, rt, ct;
    if (ti < 576)        { src = WO;   dst = g_wo;   R = DMODEL; C = DMODEL; rt = ti / 24;  ct = ti % 24; }
    else if (ti < 2880)  { int u = ti - 576;  src = Win;  dst = g_win;  R = DMODEL; C = DMLP;   rt = u / 96; ct = u % 96; }
    else                 { int u = ti - 2880; src = Wout; dst = g_wout; R = DMLP;   C = DMODEL; rt = u / 24; ct = u % 24; }
    int r0 = rt * 32, c0 = ct * 32;
    int tr = threadIdx.x >> 5, tc = threadIdx.x & 31;
#pragma unroll
    for (int i = 0; i < 4; i++)
        t[tr + i * 8][tc] = src[(size_t)(r0 + tr + i * 8) * C + c0 + tc];
    __syncthreads();
#pragma unroll
    for (int i = 0; i < 4; i++) {
        int cc = tr + i * 8;
        dst[(size_t)(c0 + cc) * R + r0 + tc] = to_tf32(t[tc][cc]);
    }
}

// ---------------- layernorm (float4, 192 threads) -> tf32-rounded f32 ----------------
__global__ __launch_bounds__(192)
void ln_kernel(const float* __restrict__ x, const float* __restrict__ w, const float* __restrict__ b,
               float* __restrict__ y) {
    __shared__ float ws[6], wq[6], stats[2];
    int row = blockIdx.x, tid = threadIdx.x;
    float4 v = ((const float4*)(x + (size_t)row * DMODEL))[tid];
    float s  = v.x + v.y + v.z + v.w;
    float sq = v.x * v.x + v.y * v.y + v.z * v.z + v.w * v.w;
#pragma unroll
    for (int o = 16; o > 0; o >>= 1) {
        s  += __shfl_xor_sync(0xffffffffu, s,  o);
        sq += __shfl_xor_sync(0xffffffffu, sq, o);
    }
    if ((tid & 31) == 0) { ws[tid >> 5] = s; wq[tid >> 5] = sq; }
    __syncthreads();
    if (tid == 0) {
        float ts = 0.f, tq = 0.f;
#pragma unroll
        for (int i = 0; i < 6; i++) { ts += ws[i]; tq += wq[i]; }
        float mean = ts * (1.0f / DMODEL);
        float var  = tq * (1.0f / DMODEL) - mean * mean;
        stats[0] = mean; stats[1] = rsqrtf(var + 1e-5f);
    }
    __syncthreads();
    float mean = stats[0], rstd = stats[1];
    float4 wv = ((const float4*)w)[tid];
    float4 bv = ((const float4*)b)[tid];
    float4 o;
    o.x = to_tf32((v.x - mean) * rstd * wv.x + bv.x);
    o.y = to_tf32((v.y - mean) * rstd * wv.y + bv.y);
    o.z = to_tf32((v.z - mean) * rstd * wv.z + bv.z);
    o.w = to_tf32((v.w - mean) * rstd * wv.w + bv.w);
    ((float4*)(y + (size_t)row * DMODEL))[tid] = o;
}

// ---------------- TF32 GEMM: C[M,N] = A[M,K] * B[N,K]^T ----------------
// 128x128 CTA tile, KC=32, 3-stage cp.async, single sync per chunk, 2 CTA/SM.
// EPI: 1 = bias+gelu->tf32 f32 ; 2 = bias+resid->f32 ; 3 = bias->bf16 hi/lo
#define TTILE 16384
#define TSTG  (2*TTILE)
#define TSMEM (1024 + 3*TSTG)

__device__ __forceinline__ void stage_tf(uint32_t tb, const float* A, const float* B,
                                         int k0, int K, int tid) {
#pragma unroll
    for (int it = 0; it < 4; it++) {
        int idx = tid + it * 256;
        int row = idx >> 3, seg = idx & 7;
        uint32_t off = SW128((uint32_t)(row * 128 + seg * 16));
        cp16(tb + off,         A + (size_t)row * K + k0 + seg * 4);
        cp16(tb + TTILE + off, B + (size_t)row * K + k0 + seg * 4);
    }
    CP_COMMIT();
}

template <int EPI>
__global__ __launch_bounds__(256, 2)
void gemm_tf32(const float* __restrict__ A, const float* __restrict__ B,
               const float* __restrict__ bias, const float* __restrict__ R,
               float* __restrict__ C, bf16* __restrict__ Chi, bf16* __restrict__ Clo,
               int N, int K, int NC) {
    extern __shared__ char smraw[];
    uint32_t sb = (smem_u32(smraw) + 1023) & ~1023u;
    int tid = threadIdx.x;
    int row0 = blockIdx.y * 128, col0 = blockIdx.x * 128;
    int wid = tid >> 5, lane = tid & 31;
    int wm = (wid >> 2) * 64, wn = (wid & 3) * 32;

    const float* Ab = A + (size_t)row0 * K;
    const float* Bb = B + (size_t)col0 * K;

    stage_tf(sb,        Ab, Bb, 0,  K, tid);
    stage_tf(sb + TSTG, Ab, Bb, 32, K, tid);

    float acc[4][4][4];
#pragma unroll
    for (int mi = 0; mi < 4; mi++)
#pragma unroll
        for (int ni = 0; ni < 4; ni++)
#pragma unroll
            for (int q = 0; q < 4; q++) acc[mi][ni][q] = 0.f;

    int ar = lane & 15, acol = (lane >> 4) * 16;
    int brt = (lane & 7) + ((lane >> 4) & 1) * 8;
    int bct = ((lane >> 3) & 1) * 16;

    for (int i = 0; i < NC; i++) {
        if (i + 2 < NC) CP_WAIT(1); else CP_WAIT(0);
        __syncthreads();
        if (i + 2 < NC)
            stage_tf(sb + (uint32_t)((i + 2) % 3) * TSTG, Ab, Bb, (i + 2) * 32, K, tid);
        uint32_t tb = sb + (uint32_t)(i % 3) * TSTG;
#pragma unroll
        for (int ks = 0; ks < 4; ks++) {
            uint32_t af[4][4], bfr[2][4];
#pragma unroll
            for (int mi = 0; mi < 4; mi++) {
                uint32_t off = SW128((uint32_t)((wm + mi * 16 + ar) * 128 + ks * 32 + acol));
                LDSM4(af[mi][0], af[mi][1], af[mi][2], af[mi][3], tb + off);
            }
#pragma unroll
            for (int nb = 0; nb < 2; nb++) {
                uint32_t off = SW128((uint32_t)((wn + nb * 16 + brt) * 128 + ks * 32 + bct));
                LDSM4(bfr[nb][0], bfr[nb][1], bfr[nb][2], bfr[nb][3], tb + TTILE + off);
            }
#pragma unroll
            for (int mi = 0; mi < 4; mi++)
#pragma unroll
                for (int ni = 0; ni < 4; ni++) {
                    int nb = ni >> 1, p = (ni & 1) * 2;
                    MMATF32(acc[mi][ni], af[mi], bfr[nb][p], bfr[nb][p + 1]);
                }
        }
    }

#pragma unroll
    for (int mi = 0; mi < 4; mi++) {
#pragma unroll
        for (int ni = 0; ni < 4; ni++) {
            int r = row0 + wm + mi * 16 + (lane >> 2);
            int c = col0 + wn + ni * 8 + (lane & 3) * 2;
            float b0 = bias[c], b1 = bias[c + 1];
#pragma unroll
            for (int half = 0; half < 2; half++) {
                int rr = r + half * 8;
                float v0 = acc[mi][ni][2 * half]     + b0;
                float v1 = acc[mi][ni][2 * half + 1] + b1;
                if (EPI == 1) {
                    *(float2*)&C[(size_t)rr * N + c] =
                        make_float2(to_tf32(gelu_new_f(v0)), to_tf32(gelu_new_f(v1)));
                } else if (EPI == 3) {
                    *(uint32_t*)&Chi[(size_t)rr * N + c] = pack_hi2(v0, v1);
                    *(uint32_t*)&Clo[(size_t)rr * N + c] = pack_lo2(v0, v1);
                } else {
                    float2 rv = *(const float2*)&R[(size_t)rr * N + c];
                    *(float2*)&C[(size_t)rr * N + c] = make_float2(v0 + rv.x, v1 + rv.y);
                }
            }
        }
    }
}

// ---------------- mma flash attention ----------------
// Q split hi/lo, K split hi/lo, V hi only, P split hi/lo.
// 3-stage KV ring (24 KB/stage), single sync per kv tile, largest-work CTAs first.
#define ASTG0 32768
#define ASTG  24576
#define ASMEM (1024 + ASTG0 + 3*ASTG)
#define NEGINF (-1e30f)

__device__ __forceinline__ void attn_stage_kv(uint32_t kb, const bf16* kh, const bf16* kl,
                                              const bf16* vh, int tid) {
#pragma unroll
    for (int it = 0; it < 2; it++) {
        int idx = tid + it * 256;
        int row = idx >> 3, seg = idx & 7;
        uint32_t off = SW128((uint32_t)(row * 128 + seg * 16));
        size_t g = (size_t)row * QKVW + seg * 8;
        cp16(kb + off,         kh + g);
        cp16(kb + 8192 + off,  kl + g);
        cp16(kb + 16384 + off, vh + g);
    }
    CP_COMMIT();
}

__global__ __launch_bounds__(256, 2)
void attn_mma(const bf16* __restrict__ qkvh, const bf16* __restrict__ qkvl,
              float* __restrict__ z) {
    extern __shared__ char smraw[];
    uint32_t sq = (smem_u32(smraw) + 1023) & ~1023u;
    uint32_t sstage = sq + ASTG0;
    int tid = threadIdx.x, wid = tid >> 5, lane = tid & 31;
    int qt = (int)gridDim.x - 1 - (int)blockIdx.x;     // largest work first
    int h = blockIdx.y, b = blockIdx.z;
    int q0 = qt * 128;
    size_t tokbase = (size_t)b * SEQ * QKVW;
    const bf16* qhp = qkvh + tokbase + (size_t)q0 * QKVW + h * DHEAD;
    const bf16* qlp = qkvl + tokbase + (size_t)q0 * QKVW + h * DHEAD;
    const bf16* khp = qkvh + tokbase + DMODEL + h * DHEAD;
    const bf16* klp = qkvl + tokbase + DMODEL + h * DHEAD;
    const bf16* vhp = qkvh + tokbase + 2 * DMODEL + h * DHEAD;

    int nkt = 2 * qt + 2;
    // prologue: Q (group 0), kv0 (group 1), kv1 (group 2)
#pragma unroll
    for (int it = 0; it < 4; it++) {
        int idx = tid + it * 256;
        int row = idx >> 3, seg = idx & 7;
        uint32_t off = SW128((uint32_t)(row * 128 + seg * 16));
        size_t g = (size_t)row * QKVW + seg * 8;
        cp16(sq + off,         qhp + g);
        cp16(sq + 16384 + off, qlp + g);
    }
    CP_COMMIT();
    attn_stage_kv(sstage, khp, klp, vhp, tid);
    attn_stage_kv(sstage + ASTG, khp + (size_t)64 * QKVW, klp + (size_t)64 * QKVW,
                  vhp + (size_t)64 * QKVW, tid);

    float o[8][4];
#pragma unroll
    for (int d = 0; d < 8; d++)
#pragma unroll
        for (int q = 0; q < 4; q++) o[d][q] = 0.f;
    float m0 = NEGINF, m1 = NEGINF, l0 = 0.f, l1 = 0.f;

    int ar = lane & 15, ahalf = lane >> 4;
    int brow = (lane & 7) + ((lane >> 4) << 3);
    int bhalf = (lane >> 3) & 1;
    int vkrow = (lane & 7) + (((lane >> 3) & 1) << 3);
    int vncol = (lane >> 4) * 8;
    int r0g = q0 + wid * 16 + (lane >> 2);

    for (int kt = 0; kt < nkt; kt++) {
        if (kt + 2 < nkt) CP_WAIT(1); else CP_WAIT(0);
        __syncthreads();
        if (kt + 2 < nkt)
            attn_stage_kv(sstage + (uint32_t)((kt + 2) % 3) * ASTG,
                          khp + (size_t)(kt + 2) * 64 * QKVW,
                          klp + (size_t)(kt + 2) * 64 * QKVW,
                          vhp + (size_t)(kt + 2) * 64 * QKVW, tid);
        uint32_t kb = sstage + (uint32_t)(kt % 3) * ASTG;

        // S = Q K^T (split-bf16, 3 products)
        float s[8][4];
#pragma unroll
        for (int ni = 0; ni < 8; ni++)
#pragma unroll
            for (int q = 0; q < 4; q++) s[ni][q] = 0.f;
#pragma unroll
        for (int ks = 0; ks < 4; ks++) {
            uint32_t ah[4], al[4];
            uint32_t offa = SW128((uint32_t)((wid * 16 + ar) * 128 + ks * 32 + ahalf * 16));
            LDSM4(ah[0], ah[1], ah[2], ah[3], sq + offa);
            LDSM4(al[0], al[1], al[2], al[3], sq + 16384 + offa);
#pragma unroll
            for (int nb = 0; nb < 4; nb++) {
                uint32_t bh[4], bl[4];
                uint32_t offb = SW128((uint32_t)((nb * 16 + brow) * 128 + ks * 32 + bhalf * 16));
                LDSM4(bh[0], bh[1], bh[2], bh[3], kb + offb);
                LDSM4(bl[0], bl[1], bl[2], bl[3], kb + 8192 + offb);
#pragma unroll
                for (int niL = 0; niL < 2; niL++) {
                    int ni = nb * 2 + niL, p = niL * 2;
                    MMA16816(s[ni], ah, bh[p], bh[p + 1]);
                    MMA16816(s[ni], ah, bl[p], bl[p + 1]);
                    MMA16816(s[ni], al, bh[p], bh[p + 1]);
                }
            }
        }

        if (kt >= 2 * qt) {
            int cbase = kt * 64 + (lane & 3) * 2;
#pragma unroll
            for (int ni = 0; ni < 8; ni++) {
                int c0 = cbase + ni * 8, c1 = c0 + 1;
                if (c0 > r0g)     s[ni][0] = NEGINF;
                if (c1 > r0g)     s[ni][1] = NEGINF;
                if (c0 > r0g + 8) s[ni][2] = NEGINF;
                if (c1 > r0g + 8) s[ni][3] = NEGINF;
            }
        }

        float tm0 = NEGINF, tm1 = NEGINF;
#pragma unroll
        for (int ni = 0; ni < 8; ni++) {
            tm0 = fmaxf(tm0, fmaxf(s[ni][0], s[ni][1]));
            tm1 = fmaxf(tm1, fmaxf(s[ni][2], s[ni][3]));
        }
        tm0 = fmaxf(tm0, __shfl_xor_sync(0xffffffffu, tm0, 1));
        tm0 = fmaxf(tm0, __shfl_xor_sync(0xffffffffu, tm0, 2));
        tm1 = fmaxf(tm1, __shfl_xor_sync(0xffffffffu, tm1, 1));
        tm1 = fmaxf(tm1, __shfl_xor_sync(0xffffffffu, tm1, 2));
        float nm0 = fmaxf(m0, tm0), nm1 = fmaxf(m1, tm1);
        float alpha0 = __expf(m0 - nm0), alpha1 = __expf(m1 - nm1);
        m0 = nm0; m1 = nm1;
        float rs0 = 0.f, rs1 = 0.f;
#pragma unroll
        for (int ni = 0; ni < 8; ni++) {
            s[ni][0] = __expf(s[ni][0] - nm0);
            s[ni][1] = __expf(s[ni][1] - nm0);
            s[ni][2] = __expf(s[ni][2] - nm1);
            s[ni][3] = __expf(s[ni][3] - nm1);
            rs0 += s[ni][0] + s[ni][1];
            rs1 += s[ni][2] + s[ni][3];
        }
        rs0 += __shfl_xor_sync(0xffffffffu, rs0, 1);
        rs0 += __shfl_xor_sync(0xffffffffu, rs0, 2);
        rs1 += __shfl_xor_sync(0xffffffffu, rs1, 1);
        rs1 += __shfl_xor_sync(0xffffffffu, rs1, 2);
        l0 = l0 * alpha0 + rs0;
        l1 = l1 * alpha1 + rs1;
#pragma unroll
        for (int d = 0; d < 8; d++) {
            o[d][0] *= alpha0; o[d][1] *= alpha0;
            o[d][2] *= alpha1; o[d][3] *= alpha1;
        }

        // O += P V   (P split hi/lo, V hi only)
#pragma unroll
        for (int ks = 0; ks < 4; ks++) {
            uint32_t pa_h[4], pa_l[4];
            pa_h[0] = pack_hi2(s[2 * ks][0], s[2 * ks][1]);
            pa_h[1] = pack_hi2(s[2 * ks][2], s[2 * ks][3]);
            pa_h[2] = pack_hi2(s[2 * ks + 1][0], s[2 * ks + 1][1]);
            pa_h[3] = pack_hi2(s[2 * ks + 1][2], s[2 * ks + 1][3]);
            pa_l[0] = pack_lo2(s[2 * ks][0], s[2 * ks][1]);
            pa_l[1] = pack_lo2(s[2 * ks][2], s[2 * ks][3]);
            pa_l[2] = pack_lo2(s[2 * ks + 1][0], s[2 * ks + 1][1]);
            pa_l[3] = pack_lo2(s[2 * ks + 1][2], s[2 * ks + 1][3]);
#pragma unroll
            for (int nb = 0; nb < 4; nb++) {
                uint32_t vh[4];
                uint32_t offv = SW128((uint32_t)((ks * 16 + vkrow) * 128 + nb * 32 + vncol * 2));
                LDSM4T(vh[0], vh[1], vh[2], vh[3], kb + 16384 + offv);
#pragma unroll
                for (int niL = 0; niL < 2; niL++) {
                    int d = nb * 2 + niL, p = niL * 2;
                    MMA16816(o[d], pa_h, vh[p], vh[p + 1]);
                    MMA16816(o[d], pa_l, vh[p], vh[p + 1]);
                }
            }
        }
    }

    float inv0 = 1.0f / l0, inv1 = 1.0f / l1;
    size_t rb0 = ((size_t)b * SEQ + q0 + wid * 16 + (lane >> 2)) * DMODEL + h * DHEAD + (lane & 3) * 2;
    size_t rb1 = rb0 + 8 * DMODEL;
#pragma unroll
    for (int d = 0; d < 8; d++) {
        *(float2*)&z[rb0 + d * 8] = make_float2(to_tf32(o[d][0] * inv0), to_tf32(o[d][1] * inv0));
        *(float2*)&z[rb1 + d * 8] = make_float2(to_tf32(o[d][2] * inv1), to_tf32(o[d][3] * inv1));
    }
}

// ---------------- launch ----------------
extern "C" void kernel_launch(void* const* d_in, const int* in_sizes, int n_in,
                              void* d_out, int out_size) {
    const float* resid_pre = (const float*)d_in[0];
    const float* WQ  = (const float*)d_in[1];
    const float* WK  = (const float*)d_in[2];
    const float* WV  = (const float*)d_in[3];
    const float* WO  = (const float*)d_in[4];
    const float* bQ  = (const float*)d_in[5];
    const float* bK  = (const float*)d_in[6];
    const float* bV  = (const float*)d_in[7];
    const float* bO  = (const float*)d_in[8];
    const float* ln1w = (const float*)d_in[9];
    const float* ln1b = (const float*)d_in[10];
    const float* ln2w = (const float*)d_in[11];
    const float* ln2b = (const float*)d_in[12];
    const float* Win  = (const float*)d_in[13];
    const float* bin  = (const float*)d_in[14];
    const float* Wout = (const float*)d_in[15];
    const float* bout = (const float*)d_in[16];
    float* out = (float*)d_out;

    float *p_xn, *p_xn2, *p_z, *p_hid, *p_wqkv, *p_wo, *p_win, *p_wout, *p_bqkv, *p_mid;
    bf16 *p_qkvh, *p_qkvl;
    cudaGetSymbolAddress((void**)&p_xn, g_xn);
    cudaGetSymbolAddress((void**)&p_xn2, g_xn2);
    cudaGetSymbolAddress((void**)&p_z, g_z);
    cudaGetSymbolAddress((void**)&p_hid, g_hid);
    cudaGetSymbolAddress((void**)&p_qkvh, g_qkv_hi);
    cudaGetSymbolAddress((void**)&p_qkvl, g_qkv_lo);
    cudaGetSymbolAddress((void**)&p_wqkv, g_wqkv);
    cudaGetSymbolAddress((void**)&p_wo, g_wo);
    cudaGetSymbolAddress((void**)&p_win, g_win);
    cudaGetSymbolAddress((void**)&p_wout, g_wout);
    cudaGetSymbolAddress((void**)&p_bqkv, g_bqkv);
    cudaGetSymbolAddress((void**)&p_mid, g_mid);

    cudaFuncSetAttribute(attn_mma, cudaFuncAttributeMaxDynamicSharedMemorySize, ASMEM);
    cudaFuncSetAttribute(gemm_tf32<1>, cudaFuncAttributeMaxDynamicSharedMemorySize, TSMEM);
    cudaFuncSetAttribute(gemm_tf32<2>, cudaFuncAttributeMaxDynamicSharedMemorySize, TSMEM);
    cudaFuncSetAttribute(gemm_tf32<3>, cudaFuncAttributeMaxDynamicSharedMemorySize, TSMEM);

    // 0) bias pack
    pack_bqkv_kernel<<<(QKVW + 255) / 256, 256>>>(bQ, bK, bV);
    // 1) QKV weight pack (merged, Q scaled 1/8)
    pack_qkvw<<<dim3(2, 24, 36), 256>>>(WQ, WK, WV);
    // 2) WO/Win/Wout pack (merged)
    pack_mlpw<<<5184, 256>>>(WO, Win, Wout);
    // 3) LN1 -> tf32 f32
    ln_kernel<<<MTOT, 192>>>(resid_pre, ln1w, ln1b, p_xn);
    // 4) QKV projection (tf32) -> bf16 hi/lo
    gemm_tf32<3><<<dim3(QKVW / 128, MTOT / 128), 256, TSMEM>>>(
        p_xn, p_wqkv, p_bqkv, nullptr, nullptr, p_qkvh, p_qkvl, QKVW, DMODEL, DMODEL / 32);
    // 5) causal flash attention
    attn_mma<<<dim3(SEQ / 128, NHEADS, BATCH), 256, ASMEM>>>(p_qkvh, p_qkvl, p_z);
    // 6) O projection + residual
    gemm_tf32<2><<<dim3(DMODEL / 128, MTOT / 128), 256, TSMEM>>>(
        p_z, p_wo, bO, resid_pre, p_mid, nullptr, nullptr, DMODEL, DMODEL, DMODEL / 32);
    // 7) LN2
    ln_kernel<<<MTOT, 192>>>(p_mid, ln2w, ln2b, p_xn2);
    // 8) MLP in + GELU
    gemm_tf32<1><<<dim3(DMLP / 128, MTOT / 128), 256, TSMEM>>>(
        p_xn2, p_win, bin, nullptr, p_hid, nullptr, nullptr, DMLP, DMODEL, DMODEL / 32);
    // 9) MLP out + residual
    gemm_tf32<2><<<dim3(DMODEL / 128, MTOT / 128), 256, TSMEM>>>(
        p_hid, p_wout, bout, p_mid, out, nullptr, nullptr, DMODEL, DMLP, DMLP / 32);
}

// round 12
// speedup vs baseline: 1.2181x; 1.0176x over previous
#include <cuda_runtime.h>
#include <cuda_bf16.h>
#include <math.h>
#include <stdint.h>

#define MTOT   8192
#define DMODEL 768
#define NHEADS 12
#define DHEAD  64
#define DMLP   3072
#define SEQ    1024
#define BATCH  8
#define QKVW   (3*DMODEL)

typedef __nv_bfloat16 bf16;

// ---------------- scratch ----------------
__device__ __align__(256) float g_xn [MTOT*DMODEL];
__device__ __align__(256) float g_xn2[MTOT*DMODEL];
__device__ __align__(256) float g_z  [MTOT*DMODEL];
__device__ __align__(256) float g_hid[(size_t)MTOT*DMLP];
__device__ __align__(256) bf16 g_qkv_hi[(size_t)MTOT*QKVW];
__device__ __align__(256) bf16 g_qkv_lo[(size_t)MTOT*QKVW];
__device__ __align__(256) float g_wqkv[QKVW*DMODEL];
__device__ __align__(256) float g_wo  [DMODEL*DMODEL];
__device__ __align__(256) float g_win [DMODEL*DMLP];
__device__ __align__(256) float g_wout[DMLP*DMODEL];
__device__ float g_bqkv[QKVW];
__device__ float g_mid [MTOT*DMODEL];

// ---------------- helpers ----------------
__device__ __forceinline__ uint32_t smem_u32(const void* p) {
    uint32_t a;
    asm("{ .reg .u64 t; cvta.to.shared.u64 t, %1; cvt.u32.u64 %0, t; }" : "=r"(a) : "l"(p));
    return a;
}
#define SW128(o) ((o) ^ (((o) >> 3) & 0x70))

__device__ __forceinline__ void cp16(uint32_t dst, const void* src) {
    asm volatile("cp.async.cg.shared.global [%0], [%1], 16;" :: "r"(dst), "l"(src));
}
#define CP_COMMIT() asm volatile("cp.async.commit_group;" ::: "memory")
#define CP_WAIT(n)  asm volatile("cp.async.wait_group %0;" :: "n"(n) : "memory")

#define LDSM4(r0, r1, r2, r3, addr) \
    asm volatile("ldmatrix.sync.aligned.m8n8.x4.shared.b16 {%0,%1,%2,%3},[%4];" \
        : "=r"(r0), "=r"(r1), "=r"(r2), "=r"(r3) : "r"(addr))
#define LDSM4T(r0, r1, r2, r3, addr) \
    asm volatile("ldmatrix.sync.aligned.m8n8.x4.trans.shared.b16 {%0,%1,%2,%3},[%4];" \
        : "=r"(r0), "=r"(r1), "=r"(r2), "=r"(r3) : "r"(addr))

#define MMA16816(d, a, b0, b1) \
    asm volatile("mma.sync.aligned.m16n8k16.row.col.f32.bf16.bf16.f32 " \
        "{%0,%1,%2,%3},{%4,%5,%6,%7},{%8,%9},{%0,%1,%2,%3};" \
        : "+f"((d)[0]), "+f"((d)[1]), "+f"((d)[2]), "+f"((d)[3]) \
        : "r"((a)[0]), "r"((a)[1]), "r"((a)[2]), "r"((a)[3]), "r"(b0), "r"(b1))

#define MMATF32(d, a, b0, b1) \
    asm volatile("mma.sync.aligned.m16n8k8.row.col.f32.tf32.tf32.f32 " \
        "{%0,%1,%2,%3},{%4,%5,%6,%7},{%8,%9},{%0,%1,%2,%3};" \
        : "+f"((d)[0]), "+f"((d)[1]), "+f"((d)[2]), "+f"((d)[3]) \
        : "r"((a)[0]), "r"((a)[1]), "r"((a)[2]), "r"((a)[3]), "r"(b0), "r"(b1))

__device__ __forceinline__ float to_tf32(float x) {
    uint32_t u;
    asm("cvt.rna.tf32.f32 %0, %1;" : "=r"(u) : "f"(x));
    return __uint_as_float(u);
}
__device__ __forceinline__ float gelu_new_f(float x) {
    float x3 = x * x * x;
    return 0.5f * x * (1.0f + tanhf(0.7978845608028654f * (x + 0.044715f * x3)));
}
__device__ __forceinline__ uint32_t pack_bf162(bf16 a, bf16 b) {
    __nv_bfloat162 t(a, b);
    return *(uint32_t*)&t;
}
__device__ __forceinline__ uint32_t pack_hi2(float a, float b) {
    return pack_bf162(__float2bfloat16(a), __float2bfloat16(b));
}
__device__ __forceinline__ uint32_t pack_lo2(float a, float b) {
    bf16 ha = __float2bfloat16(a), hb = __float2bfloat16(b);
    return pack_bf162(__float2bfloat16(a - __bfloat162float(ha)),
                      __float2bfloat16(b - __bfloat162float(hb)));
}

// ---------------- packs ----------------
__global__ void pack_bqkv_kernel(const float* __restrict__ bQ, const float* __restrict__ bK,
                                 const float* __restrict__ bV) {
    int i = threadIdx.x + blockIdx.x * 256;
    if (i >= QKVW) return;
    g_bqkv[i] = (i < DMODEL) ? bQ[i] * 0.125f : (i < 2 * DMODEL ? bK[i - DMODEL] : bV[i - 2 * DMODEL]);
}

__global__ __launch_bounds__(256)
void pack_qkvw(const float* __restrict__ WQ, const float* __restrict__ WK,
               const float* __restrict__ WV) {
    __shared__ float t[32][33];
    int z = blockIdx.z;
    int sel = z / NHEADS, h = z % NHEADS;
    const float* src = (sel == 0 ? WQ : sel == 1 ? WK : WV) + (size_t)h * DMODEL * DHEAD;
    float scale = sel == 0 ? 0.125f : 1.0f;
    int r0 = blockIdx.y * 32, c0 = blockIdx.x * 32;
    int tr = threadIdx.x >> 5, tc = threadIdx.x & 31;
#pragma unroll
    for (int i = 0; i < 4; i++)
        t[tr + i * 8][tc] = src[(size_t)(r0 + tr + i * 8) * DHEAD + c0 + tc];
    __syncthreads();
    int colbase = sel * DMODEL + h * DHEAD + c0;
#pragma unroll
    for (int i = 0; i < 4; i++) {
        int cc = tr + i * 8;
        g_wqkv[(size_t)(colbase + cc) * DMODEL + r0 + tc] = to_tf32(t[tc][cc] * scale);
    }
}

__global__ __launch_bounds__(256)
void pack_mlpw(const float* __restrict__ WO, const float* __restrict__ Win,
               const float* __restrict__ Wout) {
    __shared__ float t[32][33];
    int ti = blockIdx.x;
    const float* src; float* dst; int R, C, rt, ct;
    if (ti < 576)        { src = WO;   dst = g_wo;   R = DMODEL; C = DMODEL; rt = ti / 24;  ct = ti % 24; }
    else if (ti < 2880)  { int u = ti - 576;  src = Win;  dst = g_win;  R = DMODEL; C = DMLP;   rt = u / 96; ct = u % 96; }
    else                 { int u = ti - 2880; src = Wout; dst = g_wout; R = DMLP;   C = DMODEL; rt = u / 24; ct = u % 24; }
    int r0 = rt * 32, c0 = ct * 32;
    int tr = threadIdx.x >> 5, tc = threadIdx.x & 31;
#pragma unroll
    for (int i = 0; i < 4; i++)
        t[tr + i * 8][tc] = src[(size_t)(r0 + tr + i * 8) * C + c0 + tc];
    __syncthreads();
#pragma unroll
    for (int i = 0; i < 4; i++) {
        int cc = tr + i * 8;
        dst[(size_t)(c0 + cc) * R + r0 + tc] = to_tf32(t[tc][cc]);
    }
}

// ---------------- layernorm (float4, 192 threads) -> tf32-rounded f32 ----------------
__global__ __launch_bounds__(192)
void ln_kernel(const float* __restrict__ x, const float* __restrict__ w, const float* __restrict__ b,
               float* __restrict__ y) {
    __shared__ float ws[6], wq[6], stats[2];
    int row = blockIdx.x, tid = threadIdx.x;
    float4 v = ((const float4*)(x + (size_t)row * DMODEL))[tid];
    float s  = v.x + v.y + v.z + v.w;
    float sq = v.x * v.x + v.y * v.y + v.z * v.z + v.w * v.w;
#pragma unroll
    for (int o = 16; o > 0; o >>= 1) {
        s  += __shfl_xor_sync(0xffffffffu, s,  o);
        sq += __shfl_xor_sync(0xffffffffu, sq, o);
    }
    if ((tid & 31) == 0) { ws[tid >> 5] = s; wq[tid >> 5] = sq; }
    __syncthreads();
    if (tid == 0) {
        float ts = 0.f, tq = 0.f;
#pragma unroll
        for (int i = 0; i < 6; i++) { ts += ws[i]; tq += wq[i]; }
        float mean = ts * (1.0f / DMODEL);
        float var  = tq * (1.0f / DMODEL) - mean * mean;
        stats[0] = mean; stats[1] = rsqrtf(var + 1e-5f);
    }
    __syncthreads();
    float mean = stats[0], rstd = stats[1];
    float4 wv = ((const float4*)w)[tid];
    float4 bv = ((const float4*)b)[tid];
    float4 o;
    o.x = to_tf32((v.x - mean) * rstd * wv.x + bv.x);
    o.y = to_tf32((v.y - mean) * rstd * wv.y + bv.y);
    o.z = to_tf32((v.z - mean) * rstd * wv.z + bv.z);
    o.w = to_tf32((v.w - mean) * rstd * wv.w + bv.w);
    ((float4*)(y + (size_t)row * DMODEL))[tid] = o;
}

// ---------------- TF32 GEMM: C[M,N] = A[M,K] * B[N,K]^T ----------------
#define TTILE 16384
#define TSTG  (2*TTILE)
#define TSMEM (1024 + 3*TSTG)

__device__ __forceinline__ void stage_tf(uint32_t tb, const float* A, const float* B,
                                         int k0, int K, int tid) {
#pragma unroll
    for (int it = 0; it < 4; it++) {
        int idx = tid + it * 256;
        int row = idx >> 3, seg = idx & 7;
        uint32_t off = SW128((uint32_t)(row * 128 + seg * 16));
        cp16(tb + off,         A + (size_t)row * K + k0 + seg * 4);
        cp16(tb + TTILE + off, B + (size_t)row * K + k0 + seg * 4);
    }
    CP_COMMIT();
}

template <int EPI>
__global__ __launch_bounds__(256, 2)
void gemm_tf32(const float* __restrict__ A, const float* __restrict__ B,
               const float* __restrict__ bias, const float* __restrict__ R,
               float* __restrict__ C, bf16* __restrict__ Chi, bf16* __restrict__ Clo,
               int N, int K, int NC) {
    extern __shared__ char smraw[];
    uint32_t sb = (smem_u32(smraw) + 1023) & ~1023u;
    int tid = threadIdx.x;
    int row0 = blockIdx.y * 128, col0 = blockIdx.x * 128;
    int wid = tid >> 5, lane = tid & 31;
    int wm = (wid >> 2) * 64, wn = (wid & 3) * 32;

    const float* Ab = A + (size_t)row0 * K;
    const float* Bb = B + (size_t)col0 * K;

    stage_tf(sb,        Ab, Bb, 0,  K, tid);
    stage_tf(sb + TSTG, Ab, Bb, 32, K, tid);

    float acc[4][4][4];
#pragma unroll
    for (int mi = 0; mi < 4; mi++)
#pragma unroll
        for (int ni = 0; ni < 4; ni++)
#pragma unroll
            for (int q = 0; q < 4; q++) acc[mi][ni][q] = 0.f;

    int ar = lane & 15, acol = (lane >> 4) * 16;
    int brt = (lane & 7) + ((lane >> 4) & 1) * 8;
    int bct = ((lane >> 3) & 1) * 16;

    for (int i = 0; i < NC; i++) {
        if (i + 2 < NC) CP_WAIT(1); else CP_WAIT(0);
        __syncthreads();
        if (i + 2 < NC)
            stage_tf(sb + (uint32_t)((i + 2) % 3) * TSTG, Ab, Bb, (i + 2) * 32, K, tid);
        uint32_t tb = sb + (uint32_t)(i % 3) * TSTG;
#pragma unroll
        for (int ks = 0; ks < 4; ks++) {
            uint32_t af[4][4], bfr[2][4];
#pragma unroll
            for (int mi = 0; mi < 4; mi++) {
                uint32_t off = SW128((uint32_t)((wm + mi * 16 + ar) * 128 + ks * 32 + acol));
                LDSM4(af[mi][0], af[mi][1], af[mi][2], af[mi][3], tb + off);
            }
#pragma unroll
            for (int nb = 0; nb < 2; nb++) {
                uint32_t off = SW128((uint32_t)((wn + nb * 16 + brt) * 128 + ks * 32 + bct));
                LDSM4(bfr[nb][0], bfr[nb][1], bfr[nb][2], bfr[nb][3], tb + TTILE + off);
            }
#pragma unroll
            for (int mi = 0; mi < 4; mi++)
#pragma unroll
                for (int ni = 0; ni < 4; ni++) {
                    int nb = ni >> 1, p = (ni & 1) * 2;
                    MMATF32(acc[mi][ni], af[mi], bfr[nb][p], bfr[nb][p + 1]);
                }
        }
    }

#pragma unroll
    for (int mi = 0; mi < 4; mi++) {
#pragma unroll
        for (int ni = 0; ni < 4; ni++) {
            int r = row0 + wm + mi * 16 + (lane >> 2);
            int c = col0 + wn + ni * 8 + (lane & 3) * 2;
            float b0 = bias[c], b1 = bias[c + 1];
#pragma unroll
            for (int half = 0; half < 2; half++) {
                int rr = r + half * 8;
                float v0 = acc[mi][ni][2 * half]     + b0;
                float v1 = acc[mi][ni][2 * half + 1] + b1;
                if (EPI == 1) {
                    *(float2*)&C[(size_t)rr * N + c] =
                        make_float2(to_tf32(gelu_new_f(v0)), to_tf32(gelu_new_f(v1)));
                } else if (EPI == 3) {
                    *(uint32_t*)&Chi[(size_t)rr * N + c] = pack_hi2(v0, v1);
                    *(uint32_t*)&Clo[(size_t)rr * N + c] = pack_lo2(v0, v1);
                } else {
                    float2 rv = *(const float2*)&R[(size_t)rr * N + c];
                    *(float2*)&C[(size_t)rr * N + c] = make_float2(v0 + rv.x, v1 + rv.y);
                }
            }
        }
    }
}

// ---------------- mma flash attention ----------------
// Q split hi/lo, K hi only, V hi only, P split hi/lo.
// 4-stage KV ring (16 KB/stage), single sync per kv tile, largest-work CTAs first.
#define ASTG0 32768
#define ASTG  16384
#define ASMEM (1024 + ASTG0 + 4*ASTG)
#define NEGINF (-1e30f)

__device__ __forceinline__ void attn_stage_kv(uint32_t kb, const bf16* kh, const bf16* vh, int tid) {
#pragma unroll
    for (int it = 0; it < 2; it++) {
        int idx = tid + it * 256;
        int row = idx >> 3, seg = idx & 7;
        uint32_t off = SW128((uint32_t)(row * 128 + seg * 16));
        size_t g = (size_t)row * QKVW + seg * 8;
        cp16(kb + off,        kh + g);
        cp16(kb + 8192 + off, vh + g);
    }
    CP_COMMIT();
}

__global__ __launch_bounds__(256, 2)
void attn_mma(const bf16* __restrict__ qkvh, const bf16* __restrict__ qkvl,
              float* __restrict__ z) {
    extern __shared__ char smraw[];
    uint32_t sq = (smem_u32(smraw) + 1023) & ~1023u;
    uint32_t sstage = sq + ASTG0;
    int tid = threadIdx.x, wid = tid >> 5, lane = tid & 31;
    int qt = (int)gridDim.x - 1 - (int)blockIdx.x;     // largest work first
    int h = blockIdx.y, b = blockIdx.z;
    int q0 = qt * 128;
    size_t tokbase = (size_t)b * SEQ * QKVW;
    const bf16* qhp = qkvh + tokbase + (size_t)q0 * QKVW + h * DHEAD;
    const bf16* qlp = qkvl + tokbase + (size_t)q0 * QKVW + h * DHEAD;
    const bf16* khp = qkvh + tokbase + DMODEL + h * DHEAD;
    const bf16* vhp = qkvh + tokbase + 2 * DMODEL + h * DHEAD;

    int nkt = 2 * qt + 2;
    // prologue: Q (group 0), kv tiles 0..min(2, nkt-1)
#pragma unroll
    for (int it = 0; it < 4; it++) {
        int idx = tid + it * 256;
        int row = idx >> 3, seg = idx & 7;
        uint32_t off = SW128((uint32_t)(row * 128 + seg * 16));
        size_t g = (size_t)row * QKVW + seg * 8;
        cp16(sq + off,         qhp + g);
        cp16(sq + 16384 + off, qlp + g);
    }
    CP_COMMIT();
    attn_stage_kv(sstage,        khp,                      vhp,                      tid);
    attn_stage_kv(sstage + ASTG, khp + (size_t)64 * QKVW,  vhp + (size_t)64 * QKVW,  tid);
    if (nkt > 2)
        attn_stage_kv(sstage + 2 * ASTG, khp + (size_t)128 * QKVW, vhp + (size_t)128 * QKVW, tid);

    float o[8][4];
#pragma unroll
    for (int d = 0; d < 8; d++)
#pragma unroll
        for (int q = 0; q < 4; q++) o[d][q] = 0.f;
    float m0 = NEGINF, m1 = NEGINF, l0 = 0.f, l1 = 0.f;

    int ar = lane & 15, ahalf = lane >> 4;
    int brow = (lane & 7) + ((lane >> 4) << 3);
    int bhalf = (lane >> 3) & 1;
    int vkrow = (lane & 7) + (((lane >> 3) & 1) << 3);
    int vncol = (lane >> 4) * 8;
    int r0g = q0 + wid * 16 + (lane >> 2);

    for (int kt = 0; kt < nkt; kt++) {
        if (kt + 2 < nkt)      CP_WAIT(2);
        else if (kt + 1 < nkt) CP_WAIT(1);
        else                   CP_WAIT(0);
        __syncthreads();
        if (kt + 3 < nkt)
            attn_stage_kv(sstage + (uint32_t)((kt + 3) & 3) * ASTG,
                          khp + (size_t)(kt + 3) * 64 * QKVW,
                          vhp + (size_t)(kt + 3) * 64 * QKVW, tid);
        uint32_t kb = sstage + (uint32_t)(kt & 3) * ASTG;

        // S = Q K^T  (Q split, K hi only: 2 MMAs)
        float s[8][4];
#pragma unroll
        for (int ni = 0; ni < 8; ni++)
#pragma unroll
            for (int q = 0; q < 4; q++) s[ni][q] = 0.f;
#pragma unroll
        for (int ks = 0; ks < 4; ks++) {
            uint32_t ah[4], al[4];
            uint32_t offa = SW128((uint32_t)((wid * 16 + ar) * 128 + ks * 32 + ahalf * 16));
            LDSM4(ah[0], ah[1], ah[2], ah[3], sq + offa);
            LDSM4(al[0], al[1], al[2], al[3], sq + 16384 + offa);
#pragma unroll
            for (int nb = 0; nb < 4; nb++) {
                uint32_t bh[4];
                uint32_t offb = SW128((uint32_t)((nb * 16 + brow) * 128 + ks * 32 + bhalf * 16));
                LDSM4(bh[0], bh[1], bh[2], bh[3], kb + offb);
#pragma unroll
                for (int niL = 0; niL < 2; niL++) {
                    int ni = nb * 2 + niL, p = niL * 2;
                    MMA16816(s[ni], ah, bh[p], bh[p + 1]);
                    MMA16816(s[ni], al, bh[p], bh[p + 1]);
                }
            }
        }

        if (kt >= 2 * qt) {
            int cbase = kt * 64 + (lane & 3) * 2;
#pragma unroll
            for (int ni = 0; ni < 8; ni++) {
                int c0 = cbase + ni * 8, c1 = c0 + 1;
                if (c0 > r0g)     s[ni][0] = NEGINF;
                if (c1 > r0g)     s[ni][1] = NEGINF;
                if (c0 > r0g + 8) s[ni][2] = NEGINF;
                if (c1 > r0g + 8) s[ni][3] = NEGINF;
            }
        }

        float tm0 = NEGINF, tm1 = NEGINF;
#pragma unroll
        for (int ni = 0; ni < 8; ni++) {
            tm0 = fmaxf(tm0, fmaxf(s[ni][0], s[ni][1]));
            tm1 = fmaxf(tm1, fmaxf(s[ni][2], s[ni][3]));
        }
        tm0 = fmaxf(tm0, __shfl_xor_sync(0xffffffffu, tm0, 1));
        tm0 = fmaxf(tm0, __shfl_xor_sync(0xffffffffu, tm0, 2));
        tm1 = fmaxf(tm1, __shfl_xor_sync(0xffffffffu, tm1, 1));
        tm1 = fmaxf(tm1, __shfl_xor_sync(0xffffffffu, tm1, 2));
        float nm0 = fmaxf(m0, tm0), nm1 = fmaxf(m1, tm1);
        float alpha0 = __expf(m0 - nm0), alpha1 = __expf(m1 - nm1);
        m0 = nm0; m1 = nm1;
        float rs0 = 0.f, rs1 = 0.f;
#pragma unroll
        for (int ni = 0; ni < 8; ni++) {
            s[ni][0] = __expf(s[ni][0] - nm0);
            s[ni][1] = __expf(s[ni][1] - nm0);
            s[ni][2] = __expf(s[ni][2] - nm1);
            s[ni][3] = __expf(s[ni][3] - nm1);
            rs0 += s[ni][0] + s[ni][1];
            rs1 += s[ni][2] + s[ni][3];
        }
        rs0 += __shfl_xor_sync(0xffffffffu, rs0, 1);
        rs0 += __shfl_xor_sync(0xffffffffu, rs0, 2);
        rs1 += __shfl_xor_sync(0xffffffffu, rs1, 1);
        rs1 += __shfl_xor_sync(0xffffffffu, rs1, 2);
        l0 = l0 * alpha0 + rs0;
        l1 = l1 * alpha1 + rs1;
#pragma unroll
        for (int d = 0; d < 8; d++) {
            o[d][0] *= alpha0; o[d][1] *= alpha0;
            o[d][2] *= alpha1; o[d][3] *= alpha1;
        }

        // O += P V   (P split hi/lo, V hi only)
#pragma unroll
        for (int ks = 0; ks < 4; ks++) {
            uint32_t pa_h[4], pa_l[4];
            pa_h[0] = pack_hi2(s[2 * ks][0], s[2 * ks][1]);
            pa_h[1] = pack_hi2(s[2 * ks][2], s[2 * ks][3]);
            pa_h[2] = pack_hi2(s[2 * ks + 1][0], s[2 * ks + 1][1]);
            pa_h[3] = pack_hi2(s[2 * ks + 1][2], s[2 * ks + 1][3]);
            pa_l[0] = pack_lo2(s[2 * ks][0], s[2 * ks][1]);
            pa_l[1] = pack_lo2(s[2 * ks][2], s[2 * ks][3]);
            pa_l[2] = pack_lo2(s[2 * ks + 1][0], s[2 * ks + 1][1]);
            pa_l[3] = pack_lo2(s[2 * ks + 1][2], s[2 * ks + 1][3]);
#pragma unroll
            for (int nb = 0; nb < 4; nb++) {
                uint32_t vh[4];
                uint32_t offv = SW128((uint32_t)((ks * 16 + vkrow) * 128 + nb * 32 + vncol * 2));
                LDSM4T(vh[0], vh[1], vh[2], vh[3], kb + 8192 + offv);
#pragma unroll
                for (int niL = 0; niL < 2; niL++) {
                    int d = nb * 2 + niL, p = niL * 2;
                    MMA16816(o[d], pa_h, vh[p], vh[p + 1]);
                    MMA16816(o[d], pa_l, vh[p], vh[p + 1]);
                }
            }
        }
    }

    float inv0 = 1.0f / l0, inv1 = 1.0f / l1;
    size_t rb0 = ((size_t)b * SEQ + q0 + wid * 16 + (lane >> 2)) * DMODEL + h * DHEAD + (lane & 3) * 2;
    size_t rb1 = rb0 + 8 * DMODEL;
#pragma unroll
    for (int d = 0; d < 8; d++) {
        *(float2*)&z[rb0 + d * 8] = make_float2(to_tf32(o[d][0] * inv0), to_tf32(o[d][1] * inv0));
        *(float2*)&z[rb1 + d * 8] = make_float2(to_tf32(o[d][2] * inv1), to_tf32(o[d][3] * inv1));
    }
}

// ---------------- launch ----------------
extern "C" void kernel_launch(void* const* d_in, const int* in_sizes, int n_in,
                              void* d_out, int out_size) {
    const float* resid_pre = (const float*)d_in[0];
    const float* WQ  = (const float*)d_in[1];
    const float* WK  = (const float*)d_in[2];
    const float* WV  = (const float*)d_in[3];
    const float* WO  = (const float*)d_in[4];
    const float* bQ  = (const float*)d_in[5];
    const float* bK  = (const float*)d_in[6];
    const float* bV  = (const float*)d_in[7];
    const float* bO  = (const float*)d_in[8];
    const float* ln1w = (const float*)d_in[9];
    const float* ln1b = (const float*)d_in[10];
    const float* ln2w = (const float*)d_in[11];
    const float* ln2b = (const float*)d_in[12];
    const float* Win  = (const float*)d_in[13];
    const float* bin  = (const float*)d_in[14];
    const float* Wout = (const float*)d_in[15];
    const float* bout = (const float*)d_in[16];
    float* out = (float*)d_out;

    float *p_xn, *p_xn2, *p_z, *p_hid, *p_wqkv, *p_wo, *p_win, *p_wout, *p_bqkv, *p_mid;
    bf16 *p_qkvh, *p_qkvl;
    cudaGetSymbolAddress((void**)&p_xn, g_xn);
    cudaGetSymbolAddress((void**)&p_xn2, g_xn2);
    cudaGetSymbolAddress((void**)&p_z, g_z);
    cudaGetSymbolAddress((void**)&p_hid, g_hid);
    cudaGetSymbolAddress((void**)&p_qkvh, g_qkv_hi);
    cudaGetSymbolAddress((void**)&p_qkvl, g_qkv_lo);
    cudaGetSymbolAddress((void**)&p_wqkv, g_wqkv);
    cudaGetSymbolAddress((void**)&p_wo, g_wo);
    cudaGetSymbolAddress((void**)&p_win, g_win);
    cudaGetSymbolAddress((void**)&p_wout, g_wout);
    cudaGetSymbolAddress((void**)&p_bqkv, g_bqkv);
    cudaGetSymbolAddress((void**)&p_mid, g_mid);

    cudaFuncSetAttribute(attn_mma, cudaFuncAttributeMaxDynamicSharedMemorySize, ASMEM);
    cudaFuncSetAttribute(gemm_tf32<1>, cudaFuncAttributeMaxDynamicSharedMemorySize, TSMEM);
    cudaFuncSetAttribute(gemm_tf32<2>, cudaFuncAttributeMaxDynamicSharedMemorySize, TSMEM);
    cudaFuncSetAttribute(gemm_tf32<3>, cudaFuncAttributeMaxDynamicSharedMemorySize, TSMEM);

    // 0) bias pack
    pack_bqkv_kernel<<<(QKVW + 255) / 256, 256>>>(bQ, bK, bV);
    // 1) QKV weight pack (merged, Q scaled 1/8)
    pack_qkvw<<<dim3(2, 24, 36), 256>>>(WQ, WK, WV);
    // 2) WO/Win/Wout pack (merged)
    pack_mlpw<<<5184, 256>>>(WO, Win, Wout);
    // 3) LN1 -> tf32 f32
    ln_kernel<<<MTOT, 192>>>(resid_pre, ln1w, ln1b, p_xn);
    // 4) QKV projection (tf32) -> bf16 hi/lo
    gemm_tf32<3><<<dim3(QKVW / 128, MTOT / 128), 256, TSMEM>>>(
        p_xn, p_wqkv, p_bqkv, nullptr, nullptr, p_qkvh, p_qkvl, QKVW, DMODEL, DMODEL / 32);
    // 5) causal flash attention
    attn_mma<<<dim3(SEQ / 128, NHEADS, BATCH), 256, ASMEM>>>(p_qkvh, p_qkvl, p_z);
    // 6) O projection + residual
    gemm_tf32<2><<<dim3(DMODEL / 128, MTOT / 128), 256, TSMEM>>>(
        p_z, p_wo, bO, resid_pre, p_mid, nullptr, nullptr, DMODEL, DMODEL, DMODEL / 32);
    // 7) LN2
    ln_kernel<<<MTOT, 192>>>(p_mid, ln2w, ln2b, p_xn2);
    // 8) MLP in + GELU
    gemm_tf32<1><<<dim3(DMLP / 128, MTOT / 128), 256, TSMEM>>>(
        p_xn2, p_win, bin, nullptr, p_hid, nullptr, nullptr, DMLP, DMODEL, DMODEL / 32);
    // 9) MLP out + residual
    gemm_tf32<2><<<dim3(DMODEL / 128, MTOT / 128), 256, TSMEM>>>(
        p_hid, p_wout, bout, p_mid, out, nullptr, nullptr, DMODEL, DMLP, DMLP / 32);
}

// round 16
// speedup vs baseline: 1.2956x; 1.0637x over previous
#include <cuda_runtime.h>
#include <cuda_bf16.h>
#include <math.h>
#include <stdint.h>

#define MTOT   8192
#define DMODEL 768
#define NHEADS 12
#define DHEAD  64
#define DMLP   3072
#define SEQ    1024
#define BATCH  8
#define QKVW   (3*DMODEL)

typedef __nv_bfloat16 bf16;

// ---------------- scratch ----------------
__device__ __align__(256) float g_xn [MTOT*DMODEL];
__device__ __align__(256) float g_xn2[MTOT*DMODEL];
__device__ __align__(256) float g_z  [MTOT*DMODEL];
__device__ __align__(256) float g_hid[(size_t)MTOT*DMLP];
__device__ __align__(256) bf16 g_qkv_hi[(size_t)MTOT*QKVW];
__device__ __align__(256) float g_wqkv[QKVW*DMODEL];
__device__ __align__(256) float g_wo  [DMODEL*DMODEL];
__device__ __align__(256) float g_win [DMODEL*DMLP];
__device__ __align__(256) float g_wout[DMLP*DMODEL];
__device__ float g_bqkv[QKVW];
__device__ float g_mid [MTOT*DMODEL];

// ---------------- helpers ----------------
__device__ __forceinline__ uint32_t smem_u32(const void* p) {
    uint32_t a;
    asm("{ .reg .u64 t; cvta.to.shared.u64 t, %1; cvt.u32.u64 %0, t; }" : "=r"(a) : "l"(p));
    return a;
}
#define SW128(o) ((o) ^ (((o) >> 3) & 0x70))

__device__ __forceinline__ void cp16(uint32_t dst, const void* src) {
    asm volatile("cp.async.cg.shared.global [%0], [%1], 16;" :: "r"(dst), "l"(src));
}
#define CP_COMMIT() asm volatile("cp.async.commit_group;" ::: "memory")
#define CP_WAIT(n)  asm volatile("cp.async.wait_group %0;" :: "n"(n) : "memory")

#define LDSM4(r0, r1, r2, r3, addr) \
    asm volatile("ldmatrix.sync.aligned.m8n8.x4.shared.b16 {%0,%1,%2,%3},[%4];" \
        : "=r"(r0), "=r"(r1), "=r"(r2), "=r"(r3) : "r"(addr))
#define LDSM4T(r0, r1, r2, r3, addr) \
    asm volatile("ldmatrix.sync.aligned.m8n8.x4.trans.shared.b16 {%0,%1,%2,%3},[%4];" \
        : "=r"(r0), "=r"(r1), "=r"(r2), "=r"(r3) : "r"(addr))

#define MMA16816(d, a, b0, b1) \
    asm volatile("mma.sync.aligned.m16n8k16.row.col.f32.bf16.bf16.f32 " \
        "{%0,%1,%2,%3},{%4,%5,%6,%7},{%8,%9},{%0,%1,%2,%3};" \
        : "+f"((d)[0]), "+f"((d)[1]), "+f"((d)[2]), "+f"((d)[3]) \
        : "r"((a)[0]), "r"((a)[1]), "r"((a)[2]), "r"((a)[3]), "r"(b0), "r"(b1))

#define MMATF32(d, a, b0, b1) \
    asm volatile("mma.sync.aligned.m16n8k8.row.col.f32.tf32.tf32.f32 " \
        "{%0,%1,%2,%3},{%4,%5,%6,%7},{%8,%9},{%0,%1,%2,%3};" \
        : "+f"((d)[0]), "+f"((d)[1]), "+f"((d)[2]), "+f"((d)[3]) \
        : "r"((a)[0]), "r"((a)[1]), "r"((a)[2]), "r"((a)[3]), "r"(b0), "r"(b1))

__device__ __forceinline__ float to_tf32(float x) {
    uint32_t u;
    asm("cvt.rna.tf32.f32 %0, %1;" : "=r"(u) : "f"(x));
    return __uint_as_float(u);
}
__device__ __forceinline__ float gelu_new_f(float x) {
    float x3 = x * x * x;
    return 0.5f * x * (1.0f + tanhf(0.7978845608028654f * (x + 0.044715f * x3)));
}
__device__ __forceinline__ uint32_t pack_bf162(bf16 a, bf16 b) {
    __nv_bfloat162 t(a, b);
    return *(uint32_t*)&t;
}
__device__ __forceinline__ uint32_t pack_hi2(float a, float b) {
    return pack_bf162(__float2bfloat16(a), __float2bfloat16(b));
}

// ---------------- packs ----------------
__global__ void pack_bqkv_kernel(const float* __restrict__ bQ, const float* __restrict__ bK,
                                 const float* __restrict__ bV) {
    int i = threadIdx.x + blockIdx.x * 256;
    if (i >= QKVW) return;
    g_bqkv[i] = (i < DMODEL) ? bQ[i] * 0.125f : (i < 2 * DMODEL ? bK[i - DMODEL] : bV[i - 2 * DMODEL]);
}

__global__ __launch_bounds__(256)
void pack_qkvw(const float* __restrict__ WQ, const float* __restrict__ WK,
               const float* __restrict__ WV) {
    __shared__ float t[32][33];
    int z = blockIdx.z;
    int sel = z / NHEADS, h = z % NHEADS;
    const float* src = (sel == 0 ? WQ : sel == 1 ? WK : WV) + (size_t)h * DMODEL * DHEAD;
    float scale = sel == 0 ? 0.125f : 1.0f;
    int r0 = blockIdx.y * 32, c0 = blockIdx.x * 32;
    int tr = threadIdx.x >> 5, tc = threadIdx.x & 31;
#pragma unroll
    for (int i = 0; i < 4; i++)
        t[tr + i * 8][tc] = src[(size_t)(r0 + tr + i * 8) * DHEAD + c0 + tc];
    __syncthreads();
    int colbase = sel * DMODEL + h * DHEAD + c0;
#pragma unroll
    for (int i = 0; i < 4; i++) {
        int cc = tr + i * 8;
        g_wqkv[(size_t)(colbase + cc) * DMODEL + r0 + tc] = to_tf32(t[tc][cc] * scale);
    }
}

__global__ __launch_bounds__(256)
void pack_mlpw(const float* __restrict__ WO, const float* __restrict__ Win,
               const float* __restrict__ Wout) {
    __shared__ float t[32][33];
    int ti = blockIdx.x;
    const float* src; float* dst; int R, C, rt, ct;
    if (ti < 576)        { src = WO;   dst = g_wo;   R = DMODEL; C = DMODEL; rt = ti / 24;  ct = ti % 24; }
    else if (ti < 2880)  { int u = ti - 576;  src = Win;  dst = g_win;  R = DMODEL; C = DMLP;   rt = u / 96; ct = u % 96; }
    else                 { int u = ti - 2880; src = Wout; dst = g_wout; R = DMLP;   C = DMODEL; rt = u / 24; ct = u % 24; }
    int r0 = rt * 32, c0 = ct * 32;
    int tr = threadIdx.x >> 5, tc = threadIdx.x & 31;
#pragma unroll
    for (int i = 0; i < 4; i++)
        t[tr + i * 8][tc] = src[(size_t)(r0 + tr + i * 8) * C + c0 + tc];
    __syncthreads();
#pragma unroll
    for (int i = 0; i < 4; i++) {
        int cc = tr + i * 8;
        dst[(size_t)(c0 + cc) * R + r0 + tc] = to_tf32(t[tc][cc]);
    }
}

// ---------------- layernorm (float4, 192 threads) -> tf32-rounded f32 ----------------
__global__ __launch_bounds__(192)
void ln_kernel(const float* __restrict__ x, const float* __restrict__ w, const float* __restrict__ b,
               float* __restrict__ y) {
    __shared__ float ws[6], wq[6], stats[2];
    int row = blockIdx.x, tid = threadIdx.x;
    float4 v = ((const float4*)(x + (size_t)row * DMODEL))[tid];
    float s  = v.x + v.y + v.z + v.w;
    float sq = v.x * v.x + v.y * v.y + v.z * v.z + v.w * v.w;
#pragma unroll
    for (int o = 16; o > 0; o >>= 1) {
        s  += __shfl_xor_sync(0xffffffffu, s,  o);
        sq += __shfl_xor_sync(0xffffffffu, sq, o);
    }
    if ((tid & 31) == 0) { ws[tid >> 5] = s; wq[tid >> 5] = sq; }
    __syncthreads();
    if (tid == 0) {
        float ts = 0.f, tq = 0.f;
#pragma unroll
        for (int i = 0; i < 6; i++) { ts += ws[i]; tq += wq[i]; }
        float mean = ts * (1.0f / DMODEL);
        float var  = tq * (1.0f / DMODEL) - mean * mean;
        stats[0] = mean; stats[1] = rsqrtf(var + 1e-5f);
    }
    __syncthreads();
    float mean = stats[0], rstd = stats[1];
    float4 wv = ((const float4*)w)[tid];
    float4 bv = ((const float4*)b)[tid];
    float4 o;
    o.x = to_tf32((v.x - mean) * rstd * wv.x + bv.x);
    o.y = to_tf32((v.y - mean) * rstd * wv.y + bv.y);
    o.z = to_tf32((v.z - mean) * rstd * wv.z + bv.z);
    o.w = to_tf32((v.w - mean) * rstd * wv.w + bv.w);
    ((float4*)(y + (size_t)row * DMODEL))[tid] = o;
}

// ---------------- TF32 GEMM: C[M,N] = A[M,K] * B[N,K]^T ----------------
#define TTILE 16384
#define TSTG  (2*TTILE)
#define TSMEM (1024 + 3*TSTG)

__device__ __forceinline__ void stage_tf(uint32_t tb, const float* A, const float* B,
                                         int k0, int K, int tid) {
#pragma unroll
    for (int it = 0; it < 4; it++) {
        int idx = tid + it * 256;
        int row = idx >> 3, seg = idx & 7;
        uint32_t off = SW128((uint32_t)(row * 128 + seg * 16));
        cp16(tb + off,         A + (size_t)row * K + k0 + seg * 4);
        cp16(tb + TTILE + off, B + (size_t)row * K + k0 + seg * 4);
    }
    CP_COMMIT();
}

template <int EPI>
__global__ __launch_bounds__(256, 2)
void gemm_tf32(const float* __restrict__ A, const float* __restrict__ B,
               const float* __restrict__ bias, const float* __restrict__ R,
               float* __restrict__ C, bf16* __restrict__ Chi,
               int N, int K, int NC) {
    extern __shared__ char smraw[];
    uint32_t sb = (smem_u32(smraw) + 1023) & ~1023u;
    int tid = threadIdx.x;
    int row0 = blockIdx.y * 128, col0 = blockIdx.x * 128;
    int wid = tid >> 5, lane = tid & 31;
    int wm = (wid >> 2) * 64, wn = (wid & 3) * 32;

    const float* Ab = A + (size_t)row0 * K;
    const float* Bb = B + (size_t)col0 * K;

    stage_tf(sb,        Ab, Bb, 0,  K, tid);
    stage_tf(sb + TSTG, Ab, Bb, 32, K, tid);

    float acc[4][4][4];
#pragma unroll
    for (int mi = 0; mi < 4; mi++)
#pragma unroll
        for (int ni = 0; ni < 4; ni++)
#pragma unroll
            for (int q = 0; q < 4; q++) acc[mi][ni][q] = 0.f;

    int ar = lane & 15, acol = (lane >> 4) * 16;
    int brt = (lane & 7) + ((lane >> 4) & 1) * 8;
    int bct = ((lane >> 3) & 1) * 16;

    for (int i = 0; i < NC; i++) {
        if (i + 2 < NC) CP_WAIT(1); else CP_WAIT(0);
        __syncthreads();
        if (i + 2 < NC)
            stage_tf(sb + (uint32_t)((i + 2) % 3) * TSTG, Ab, Bb, (i + 2) * 32, K, tid);
        uint32_t tb = sb + (uint32_t)(i % 3) * TSTG;
#pragma unroll
        for (int ks = 0; ks < 4; ks++) {
            uint32_t af[4][4], bfr[2][4];
#pragma unroll
            for (int mi = 0; mi < 4; mi++) {
                uint32_t off = SW128((uint32_t)((wm + mi * 16 + ar) * 128 + ks * 32 + acol));
                LDSM4(af[mi][0], af[mi][1], af[mi][2], af[mi][3], tb + off);
            }
#pragma unroll
            for (int nb = 0; nb < 2; nb++) {
                uint32_t off = SW128((uint32_t)((wn + nb * 16 + brt) * 128 + ks * 32 + bct));
                LDSM4(bfr[nb][0], bfr[nb][1], bfr[nb][2], bfr[nb][3], tb + TTILE + off);
            }
#pragma unroll
            for (int mi = 0; mi < 4; mi++)
#pragma unroll
                for (int ni = 0; ni < 4; ni++) {
                    int nb = ni >> 1, p = (ni & 1) * 2;
                    MMATF32(acc[mi][ni], af[mi], bfr[nb][p], bfr[nb][p + 1]);
                }
        }
    }

#pragma unroll
    for (int mi = 0; mi < 4; mi++) {
#pragma unroll
        for (int ni = 0; ni < 4; ni++) {
            int r = row0 + wm + mi * 16 + (lane >> 2);
            int c = col0 + wn + ni * 8 + (lane & 3) * 2;
            float b0 = bias[c], b1 = bias[c + 1];
#pragma unroll
            for (int half = 0; half < 2; half++) {
                int rr = r + half * 8;
                float v0 = acc[mi][ni][2 * half]     + b0;
                float v1 = acc[mi][ni][2 * half + 1] + b1;
                if (EPI == 1) {
                    *(float2*)&C[(size_t)rr * N + c] =
                        make_float2(to_tf32(gelu_new_f(v0)), to_tf32(gelu_new_f(v1)));
                } else if (EPI == 3) {
                    *(uint32_t*)&Chi[(size_t)rr * N + c] = pack_hi2(v0, v1);
                } else {
                    float2 rv = *(const float2*)&R[(size_t)rr * N + c];
                    *(float2*)&C[(size_t)rr * N + c] = make_float2(v0 + rv.x, v1 + rv.y);
                }
            }
        }
    }
}

// ---------------- mma flash attention (all-bf16-hi, fp32 accum) ----------------
// Q/K/V/P all bf16 hi. 4-stage KV ring (16 KB/stage), single sync per tile,
// largest-work CTAs first.
#define ASTG0 16384
#define ASTG  16384
#define ASMEM (1024 + ASTG0 + 4*ASTG)
#define NEGINF (-1e30f)

__device__ __forceinline__ void attn_stage_kv(uint32_t kb, const bf16* kh, const bf16* vh, int tid) {
#pragma unroll
    for (int it = 0; it < 2; it++) {
        int idx = tid + it * 256;
        int row = idx >> 3, seg = idx & 7;
        uint32_t off = SW128((uint32_t)(row * 128 + seg * 16));
        size_t g = (size_t)row * QKVW + seg * 8;
        cp16(kb + off,        kh + g);
        cp16(kb + 8192 + off, vh + g);
    }
    CP_COMMIT();
}

__global__ __launch_bounds__(256, 2)
void attn_mma(const bf16* __restrict__ qkvh, float* __restrict__ z) {
    extern __shared__ char smraw[];
    uint32_t sq = (smem_u32(smraw) + 1023) & ~1023u;
    uint32_t sstage = sq + ASTG0;
    int tid = threadIdx.x, wid = tid >> 5, lane = tid & 31;
    int qt = (int)gridDim.x - 1 - (int)blockIdx.x;     // largest work first
    int h = blockIdx.y, b = blockIdx.z;
    int q0 = qt * 128;
    size_t tokbase = (size_t)b * SEQ * QKVW;
    const bf16* qhp = qkvh + tokbase + (size_t)q0 * QKVW + h * DHEAD;
    const bf16* khp = qkvh + tokbase + DMODEL + h * DHEAD;
    const bf16* vhp = qkvh + tokbase + 2 * DMODEL + h * DHEAD;

    int nkt = 2 * qt + 2;
    // prologue: Q hi — 128 rows x 8 segs = 1024 chunks -> 4 iterations x 256 threads
#pragma unroll
    for (int it = 0; it < 4; it++) {
        int idx = tid + it * 256;
        int row = idx >> 3, seg = idx & 7;
        uint32_t off = SW128((uint32_t)(row * 128 + seg * 16));
        cp16(sq + off, qhp + (size_t)row * QKVW + seg * 8);
    }
    CP_COMMIT();
    attn_stage_kv(sstage,        khp,                      vhp,                      tid);
    attn_stage_kv(sstage + ASTG, khp + (size_t)64 * QKVW,  vhp + (size_t)64 * QKVW,  tid);
    if (nkt > 2)
        attn_stage_kv(sstage + 2 * ASTG, khp + (size_t)128 * QKVW, vhp + (size_t)128 * QKVW, tid);

    float o[8][4];
#pragma unroll
    for (int d = 0; d < 8; d++)
#pragma unroll
        for (int q = 0; q < 4; q++) o[d][q] = 0.f;
    float m0 = NEGINF, m1 = NEGINF, l0 = 0.f, l1 = 0.f;

    int ar = lane & 15, ahalf = lane >> 4;
    int brow = (lane & 7) + ((lane >> 4) << 3);
    int bhalf = (lane >> 3) & 1;
    int vkrow = (lane & 7) + (((lane >> 3) & 1) << 3);
    int vncol = (lane >> 4) * 8;
    int r0g = q0 + wid * 16 + (lane >> 2);

    for (int kt = 0; kt < nkt; kt++) {
        if (kt + 2 < nkt)      CP_WAIT(2);
        else if (kt + 1 < nkt) CP_WAIT(1);
        else                   CP_WAIT(0);
        __syncthreads();
        if (kt + 3 < nkt)
            attn_stage_kv(sstage + (uint32_t)((kt + 3) & 3) * ASTG,
                          khp + (size_t)(kt + 3) * 64 * QKVW,
                          vhp + (size_t)(kt + 3) * 64 * QKVW, tid);
        uint32_t kb = sstage + (uint32_t)(kt & 3) * ASTG;

        // S = Q K^T  (bf16 hi only: 1 MMA per step)
        float s[8][4];
#pragma unroll
        for (int ni = 0; ni < 8; ni++)
#pragma unroll
            for (int q = 0; q < 4; q++) s[ni][q] = 0.f;
#pragma unroll
        for (int ks = 0; ks < 4; ks++) {
            uint32_t ah[4];
            uint32_t offa = SW128((uint32_t)((wid * 16 + ar) * 128 + ks * 32 + ahalf * 16));
            LDSM4(ah[0], ah[1], ah[2], ah[3], sq + offa);
#pragma unroll
            for (int nb = 0; nb < 4; nb++) {
                uint32_t bh[4];
                uint32_t offb = SW128((uint32_t)((nb * 16 + brow) * 128 + ks * 32 + bhalf * 16));
                LDSM4(bh[0], bh[1], bh[2], bh[3], kb + offb);
#pragma unroll
                for (int niL = 0; niL < 2; niL++) {
                    int ni = nb * 2 + niL, p = niL * 2;
                    MMA16816(s[ni], ah, bh[p], bh[p + 1]);
                }
            }
        }

        if (kt >= 2 * qt) {
            int cbase = kt * 64 + (lane & 3) * 2;
#pragma unroll
            for (int ni = 0; ni < 8; ni++) {
                int c0 = cbase + ni * 8, c1 = c0 + 1;
                if (c0 > r0g)     s[ni][0] = NEGINF;
                if (c1 > r0g)     s[ni][1] = NEGINF;
                if (c0 > r0g + 8) s[ni][2] = NEGINF;
                if (c1 > r0g + 8) s[ni][3] = NEGINF;
            }
        }

        float tm0 = NEGINF, tm1 = NEGINF;
#pragma unroll
        for (int ni = 0; ni < 8; ni++) {
            tm0 = fmaxf(tm0, fmaxf(s[ni][0], s[ni][1]));
            tm1 = fmaxf(tm1, fmaxf(s[ni][2], s[ni][3]));
        }
        tm0 = fmaxf(tm0, __shfl_xor_sync(0xffffffffu, tm0, 1));
        tm0 = fmaxf(tm0, __shfl_xor_sync(0xffffffffu, tm0, 2));
        tm1 = fmaxf(tm1, __shfl_xor_sync(0xffffffffu, tm1, 1));
        tm1 = fmaxf(tm1, __shfl_xor_sync(0xffffffffu, tm1, 2));
        float nm0 = fmaxf(m0, tm0), nm1 = fmaxf(m1, tm1);
        float alpha0 = __expf(m0 - nm0), alpha1 = __expf(m1 - nm1);
        m0 = nm0; m1 = nm1;
        float rs0 = 0.f, rs1 = 0.f;
#pragma unroll
        for (int ni = 0; ni < 8; ni++) {
            s[ni][0] = __expf(s[ni][0] - nm0);
            s[ni][1] = __expf(s[ni][1] - nm0);
            s[ni][2] = __expf(s[ni][2] - nm1);
            s[ni][3] = __expf(s[ni][3] - nm1);
            rs0 += s[ni][0] + s[ni][1];
            rs1 += s[ni][2] + s[ni][3];
        }
        rs0 += __shfl_xor_sync(0xffffffffu, rs0, 1);
        rs0 += __shfl_xor_sync(0xffffffffu, rs0, 2);
        rs1 += __shfl_xor_sync(0xffffffffu, rs1, 1);
        rs1 += __shfl_xor_sync(0xffffffffu, rs1, 2);
        l0 = l0 * alpha0 + rs0;
        l1 = l1 * alpha1 + rs1;
#pragma unroll
        for (int d = 0; d < 8; d++) {
            o[d][0] *= alpha0; o[d][1] *= alpha0;
            o[d][2] *= alpha1; o[d][3] *= alpha1;
        }

        // O += P V  (P hi, V hi)
#pragma unroll
        for (int ks = 0; ks < 4; ks++) {
            uint32_t pa_h[4];
            pa_h[0] = pack_hi2(s[2 * ks][0], s[2 * ks][1]);
            pa_h[1] = pack_hi2(s[2 * ks][2], s[2 * ks][3]);
            pa_h[2] = pack_hi2(s[2 * ks + 1][0], s[2 * ks + 1][1]);
            pa_h[3] = pack_hi2(s[2 * ks + 1][2], s[2 * ks + 1][3]);
#pragma unroll
            for (int nb = 0; nb < 4; nb++) {
                uint32_t vh[4];
                uint32_t offv = SW128((uint32_t)((ks * 16 + vkrow) * 128 + nb * 32 + vncol * 2));
                LDSM4T(vh[0], vh[1], vh[2], vh[3], kb + 8192 + offv);
#pragma unroll
                for (int niL = 0; niL < 2; niL++) {
                    int d = nb * 2 + niL, p = niL * 2;
                    MMA16816(o[d], pa_h, vh[p], vh[p + 1]);
                }
            }
        }
    }

    float inv0 = 1.0f / l0, inv1 = 1.0f / l1;
    size_t rb0 = ((size_t)b * SEQ + q0 + wid * 16 + (lane >> 2)) * DMODEL + h * DHEAD + (lane & 3) * 2;
    size_t rb1 = rb0 + 8 * DMODEL;
#pragma unroll
    for (int d = 0; d < 8; d++) {
        *(float2*)&z[rb0 + d * 8] = make_float2(to_tf32(o[d][0] * inv0), to_tf32(o[d][1] * inv0));
        *(float2*)&z[rb1 + d * 8] = make_float2(to_tf32(o[d][2] * inv1), to_tf32(o[d][3] * inv1));
    }
}

// ---------------- launch ----------------
extern "C" void kernel_launch(void* const* d_in, const int* in_sizes, int n_in,
                              void* d_out, int out_size) {
    const float* resid_pre = (const float*)d_in[0];
    const float* WQ  = (const float*)d_in[1];
    const float* WK  = (const float*)d_in[2];
    const float* WV  = (const float*)d_in[3];
    const float* WO  = (const float*)d_in[4];
    const float* bQ  = (const float*)d_in[5];
    const float* bK  = (const float*)d_in[6];
    const float* bV  = (const float*)d_in[7];
    const float* bO  = (const float*)d_in[8];
    const float* ln1w = (const float*)d_in[9];
    const float* ln1b = (const float*)d_in[10];
    const float* ln2w = (const float*)d_in[11];
    const float* ln2b = (const float*)d_in[12];
    const float* Win  = (const float*)d_in[13];
    const float* bin  = (const float*)d_in[14];
    const float* Wout = (const float*)d_in[15];
    const float* bout = (const float*)d_in[16];
    float* out = (float*)d_out;

    float *p_xn, *p_xn2, *p_z, *p_hid, *p_wqkv, *p_wo, *p_win, *p_wout, *p_bqkv, *p_mid;
    bf16 *p_qkvh;
    cudaGetSymbolAddress((void**)&p_xn, g_xn);
    cudaGetSymbolAddress((void**)&p_xn2, g_xn2);
    cudaGetSymbolAddress((void**)&p_z, g_z);
    cudaGetSymbolAddress((void**)&p_hid, g_hid);
    cudaGetSymbolAddress((void**)&p_qkvh, g_qkv_hi);
    cudaGetSymbolAddress((void**)&p_wqkv, g_wqkv);
    cudaGetSymbolAddress((void**)&p_wo, g_wo);
    cudaGetSymbolAddress((void**)&p_win, g_win);
    cudaGetSymbolAddress((void**)&p_wout, g_wout);
    cudaGetSymbolAddress((void**)&p_bqkv, g_bqkv);
    cudaGetSymbolAddress((void**)&p_mid, g_mid);

    cudaFuncSetAttribute(attn_mma, cudaFuncAttributeMaxDynamicSharedMemorySize, ASMEM);
    cudaFuncSetAttribute(gemm_tf32<1>, cudaFuncAttributeMaxDynamicSharedMemorySize, TSMEM);
    cudaFuncSetAttribute(gemm_tf32<2>, cudaFuncAttributeMaxDynamicSharedMemorySize, TSMEM);
    cudaFuncSetAttribute(gemm_tf32<3>, cudaFuncAttributeMaxDynamicSharedMemorySize, TSMEM);

    // 0) bias pack
    pack_bqkv_kernel<<<(QKVW + 255) / 256, 256>>>(bQ, bK, bV);
    // 1) QKV weight pack (merged, Q scaled 1/8)
    pack_qkvw<<<dim3(2, 24, 36), 256>>>(WQ, WK, WV);
    // 2) WO/Win/Wout pack (merged)
    pack_mlpw<<<5184, 256>>>(WO, Win, Wout);
    // 3) LN1 -> tf32 f32
    ln_kernel<<<MTOT, 192>>>(resid_pre, ln1w, ln1b, p_xn);
    // 4) QKV projection (tf32) -> bf16 hi
    gemm_tf32<3><<<dim3(QKVW / 128, MTOT / 128), 256, TSMEM>>>(
        p_xn, p_wqkv, p_bqkv, nullptr, nullptr, p_qkvh, QKVW, DMODEL, DMODEL / 32);
    // 5) causal flash attention (all-bf16-hi)
    attn_mma<<<dim3(SEQ / 128, NHEADS, BATCH), 256, ASMEM>>>(p_qkvh, p_z);
    // 6) O projection + residual
    gemm_tf32<2><<<dim3(DMODEL / 128, MTOT / 128), 256, TSMEM>>>(
        p_z, p_wo, bO, resid_pre, p_mid, nullptr, DMODEL, DMODEL, DMODEL / 32);
    // 7) LN2
    ln_kernel<<<MTOT, 192>>>(p_mid, ln2w, ln2b, p_xn2);
    // 8) MLP in + GELU
    gemm_tf32<1><<<dim3(DMLP / 128, MTOT / 128), 256, TSMEM>>>(
        p_xn2, p_win, bin, nullptr, p_hid, nullptr, DMLP, DMODEL, DMODEL / 32);
    // 9) MLP out + residual
    gemm_tf32<2><<<dim3(DMODEL / 128, MTOT / 128), 256, TSMEM>>>(
        p_hid, p_wout, bout, p_mid, out, nullptr, DMODEL, DMLP, DMLP / 32);
}